// round 13
// baseline (speedup 1.0000x reference)
#include <cuda_runtime.h>
#include <cuda_fp16.h>
#include <cuda_bf16.h>
#include <cstdint>

#define Nn   32
#define CIN  64
#define COUT 128
#define Vv   25
#define Tlen 300
#define Ss   3
#define VT   7500
#define VV   625
#define EPSf 1e-5f
#define FS   312   // padded feat row length (halves)

typedef unsigned long long u64;

// ---- device scratch (allocation-free) ----
// g_feat layout: [n][o][80 rows (s*25+w)][FS cols (t)] fp16, pre-padded tile.
// Rows 75..79 and cols 300..311 are NEVER written -> stay zero (static init).
__device__ __align__(16) __half g_feat[(size_t)Nn * COUT * 80 * FS];  // 204 MB
__device__ __align__(16) float  g_A[Ss * Nn * COUT * VV];             // 30.7 MB
__device__ __align__(16) __half g_Xhi[Nn * CIN * VT];
__device__ __align__(16) __half g_Xlo[Nn * CIN * VT];
__device__ __align__(16) __half g_Whi[512 * 64];
__device__ __align__(16) __half g_Wlo[512 * 64];
__device__ __align__(16) float g_bias[512];

// ---- scalar/FMA2 helpers ----
__device__ __forceinline__ void fma2(u64& d, u64 a, u64 b) {
    asm("fma.rn.f32x2 %0, %1, %2, %0;" : "+l"(d) : "l"(a), "l"(b));
}
__device__ __forceinline__ u64 dup2(float v) {
    u64 r; asm("mov.b64 %0, {%1, %1};" : "=l"(r) : "f"(v)); return r;
}
__device__ __forceinline__ u64 pack2(float lo, float hi) {
    u64 r; asm("mov.b64 %0, {%1, %2};" : "=l"(r) : "f"(lo), "f"(hi)); return r;
}
__device__ __forceinline__ float lo32(u64 v) { return __uint_as_float((unsigned)v); }
__device__ __forceinline__ float hi32(u64 v) { return __uint_as_float((unsigned)(v >> 32)); }

__device__ __forceinline__ uint32_t smem_u32(const void* p) {
    uint32_t a;
    asm("{ .reg .u64 t; cvta.to.shared.u64 t, %1; cvt.u32.u64 %0, t; }" : "=r"(a) : "l"(p));
    return a;
}

// ---- mma.sync / ldmatrix ----
#define LDSM_X4(r, addr) \
    asm volatile("ldmatrix.sync.aligned.m8n8.x4.shared.b16 {%0,%1,%2,%3}, [%4];" \
        : "=r"((r)[0]), "=r"((r)[1]), "=r"((r)[2]), "=r"((r)[3]) : "r"(addr))
#define LDSM_X2T(r, addr) \
    asm volatile("ldmatrix.sync.aligned.m8n8.x2.trans.shared.b16 {%0,%1}, [%2];" \
        : "=r"((r)[0]), "=r"((r)[1]) : "r"(addr))
#define MMA_F16(d, a, b) \
    asm volatile("mma.sync.aligned.m16n8k16.row.col.f32.f16.f16.f32 " \
        "{%0,%1,%2,%3}, {%4,%5,%6,%7}, {%8,%9}, {%0,%1,%2,%3};" \
        : "+f"((d)[0]), "+f"((d)[1]), "+f"((d)[2]), "+f"((d)[3]) \
        : "r"((a)[0]), "r"((a)[1]), "r"((a)[2]), "r"((a)[3]), "r"((b)[0]), "r"((b)[1]))

// ---------------------------------------------------------------------------
// kX: pre-split x (fp32) into fp16 hi/lo, linear layout identical to x.
// ---------------------------------------------------------------------------
__global__ void kX(const float* __restrict__ x) {
    size_t i4 = ((size_t)blockIdx.x * blockDim.x + threadIdx.x) * 4;
    if (i4 >= (size_t)Nn * CIN * VT) return;
    float4 v = *(const float4*)(x + i4);
    __half h0 = __float2half_rn(v.x), h1 = __float2half_rn(v.y);
    __half h2 = __float2half_rn(v.z), h3 = __float2half_rn(v.w);
    __half2 p0(h0, h1), p1(h2, h3);
    uint2 ph; ph.x = *(unsigned*)&p0; ph.y = *(unsigned*)&p1;
    *(uint2*)(g_Xhi + i4) = ph;
    __half2 q0(__float2half_rn(v.x - __half2float(h0)), __float2half_rn(v.y - __half2float(h1)));
    __half2 q1(__float2half_rn(v.z - __half2float(h2)), __float2half_rn(v.w - __half2float(h3)));
    uint2 pl; pl.x = *(unsigned*)&q0; pl.y = *(unsigned*)&q1;
    *(uint2*)(g_Xlo + i4) = pl;
}

// ---------------------------------------------------------------------------
// kW: split folded W into fp16 hi/lo + bias
// ---------------------------------------------------------------------------
__global__ void kW(const float* __restrict__ conv3_w, const float* __restrict__ conv3_b,
                   const float* __restrict__ down_w,  const float* __restrict__ down_b,
                   const float* __restrict__ dg, const float* __restrict__ dbeta,
                   const float* __restrict__ dm, const float* __restrict__ dvar) {
    int idx = blockIdx.x * blockDim.x + threadIdx.x;
    if (idx >= 512 * 64) return;
    int r = idx >> 6, k = idx & 63;
    float w;
    if (r < Ss * COUT) {
        w = conv3_w[r * CIN + k];
    } else {
        int o = r - Ss * COUT;
        w = dg[o] * rsqrtf(dvar[o] + EPSf) * down_w[o * CIN + k];
    }
    __half hi = __float2half_rn(w);
    g_Whi[idx] = hi;
    g_Wlo[idx] = __float2half_rn(w - __half2float(hi));
    if (k == 0) {
        float b;
        if (r < Ss * COUT) b = conv3_b[r];
        else {
            int o = r - Ss * COUT;
            float sc = dg[o] * rsqrtf(dvar[o] + EPSf);
            b = sc * (down_b[o] - dm[o]) + dbeta[o];
        }
        g_bias[r] = b;
    }
}

// ---------------------------------------------------------------------------
// kA: g_A = (ada_w . ada_A + ada_b) * PA. grid (20, n, s), 128 threads, FMA2.
// ---------------------------------------------------------------------------
#define KA_SMEM (64 * 16 * 8 + 64 * 125 * 4 + 32 * 4)
__global__ void __launch_bounds__(128)
kA(const float* __restrict__ adaA, const float* __restrict__ PA,
   const float* __restrict__ ada_w, const float* __restrict__ ada_b) {
    extern __shared__ char smA[];
    u64*   Wp  = (u64*)smA;
    float* Xa  = (float*)(smA + 64 * 16 * 8);
    float* bsm = (float*)(smA + 64 * 16 * 8 + 64 * 125 * 4);

    int tid = threadIdx.x;
    int s = blockIdx.z, n = blockIdx.y;
    int g = blockIdx.x & 3;
    int vw0 = (blockIdx.x >> 2) * 125;

    const float* wsrc = ada_w + s * COUT * CIN + g * 32 * CIN;
    for (int idx = tid; idx < 64 * 16; idx += 128) {
        int i = idx >> 4, op = idx & 15;
        Wp[i * 16 + op] = pack2(wsrc[(2 * op) * CIN + i], wsrc[(2 * op + 1) * CIN + i]);
    }
    for (int idx = tid; idx < 64 * 125; idx += 128) {
        int i = idx / 125, j = idx % 125;
        Xa[i * 125 + j] = adaA[(size_t)(n * CIN + i) * VV + vw0 + j];
    }
    if (tid < 32) bsm[tid] = ada_b[s * COUT + g * 32 + tid];
    __syncthreads();
    if (tid >= 125) return;

    int vw = vw0 + tid;
    float pa = PA[s * VV + vw];

    u64 acc[16];
#pragma unroll
    for (int p = 0; p < 16; p++) acc[p] = 0ull;

#pragma unroll 8
    for (int i = 0; i < CIN; i++) {
        u64 f2 = dup2(Xa[i * 125 + tid]);
        const ulonglong2* wr = (const ulonglong2*)(Wp + i * 16);
#pragma unroll
        for (int p = 0; p < 8; p++) {
            ulonglong2 wv = wr[p];
            fma2(acc[2 * p],     wv.x, f2);
            fma2(acc[2 * p + 1], wv.y, f2);
        }
    }
    float* outp = g_A + ((size_t)((s * Nn + n) * COUT) + g * 32) * VV + vw;
#pragma unroll
    for (int p = 0; p < 16; p++) {
        outp[(size_t)(2 * p) * VV]     = (lo32(acc[p]) + bsm[2 * p])     * pa;
        outp[(size_t)(2 * p + 1) * VV] = (hi32(acc[p]) + bsm[2 * p + 1]) * pa;
    }
}

// ---------------------------------------------------------------------------
// kB_m: tensor GEMM C[128r x 128c] = W[128x64] @ X[64 x 128c].
// feat CTAs (rg<3): fragments stored DIRECTLY to padded g_feat tiles (no smem
// epilogue, no extra barriers). res CTA (rg==3): Cs smem path for coalesced
// float4 stores to d_out. grid (59, 4, 32), 512 threads, 2 CTAs/SM.
// ---------------------------------------------------------------------------
#define PADK 72
#define PADC 136
#define WHI_OFF 0
#define WLO_OFF (128 * PADK * 2)
#define XHI_OFF (WLO_OFF + 128 * PADK * 2)
#define XLO_OFF (XHI_OFF + 64 * PADC * 2)
#define BIAS_OFF (XLO_OFF + 64 * PADC * 2)
#define KBM_SMEM (BIAS_OFF + 128 * 4)
__global__ void __launch_bounds__(512, 2)
kB_m(float* __restrict__ out) {
    extern __shared__ char sm[];
    __half* Whi_s = (__half*)(sm + WHI_OFF);
    __half* Wlo_s = (__half*)(sm + WLO_OFF);
    __half* Xhi_s = (__half*)(sm + XHI_OFF);
    __half* Xlo_s = (__half*)(sm + XLO_OFF);
    float* bias_s = (float*)(sm + BIAS_OFF);
    float* Cs = (float*)sm;

    int tid = threadIdx.x;
    int wid = tid >> 5, lane = tid & 31;
    int n = blockIdx.z, rg = blockIdx.y;
    int c0 = blockIdx.x * 128;
    int r0 = rg * 128;
    int ncols = VT - c0; if (ncols > 128) ncols = 128;
    bool isRes = (rg == 3);
    int w0 = c0 / 300;
    int rem0 = c0 - w0 * 300;

    for (int idx = tid; idx < 1024; idx += 512) {
        int row = idx >> 3, kc = (idx & 7) * 8;
        uint4 v = *(const uint4*)(g_Whi + (size_t)(r0 + row) * 64 + kc);
        *(uint4*)(Whi_s + row * PADK + kc) = v;
    }
    if (isRes) {
        for (int idx = tid; idx < 1024; idx += 512) {
            int row = idx >> 3, kc = (idx & 7) * 8;
            uint4 v = *(const uint4*)(g_Wlo + (size_t)(r0 + row) * 64 + kc);
            *(uint4*)(Wlo_s + row * PADK + kc) = v;
        }
    }
    if (tid < 128) bias_s[tid] = g_bias[r0 + tid];

    for (int idx = tid; idx < 64 * 32; idx += 512) {
        int k = idx >> 5, c4 = (idx & 31) << 2;
        uint2 v = make_uint2(0u, 0u);
        if (c4 < ncols) v = *(const uint2*)(g_Xhi + (size_t)(n * CIN + k) * VT + c0 + c4);
        *(uint2*)(Xhi_s + k * PADC + c4) = v;
        if (isRes) {
            uint2 vl = make_uint2(0u, 0u);
            if (c4 < ncols) vl = *(const uint2*)(g_Xlo + (size_t)(n * CIN + k) * VT + c0 + c4);
            *(uint2*)(Xlo_s + k * PADC + c4) = vl;
        }
    }
    __syncthreads();

    int wm0 = (wid & 3) * 32;
    int wn0 = (wid >> 2) * 32;
    uint32_t sbase = smem_u32(sm);

    float acc[2][4][4];
#pragma unroll
    for (int mi = 0; mi < 2; mi++)
#pragma unroll
        for (int ni = 0; ni < 4; ni++)
#pragma unroll
            for (int q = 0; q < 4; q++) acc[mi][ni][q] = 0.f;

#pragma unroll
    for (int k0 = 0; k0 < 64; k0 += 16) {
        uint32_t a_hi[2][4], b_hi[4][2];
#pragma unroll
        for (int mi = 0; mi < 2; mi++) {
            int row = wm0 + mi * 16 + (lane & 15);
            int col = k0 + (lane >> 4) * 8;
            LDSM_X4(a_hi[mi], sbase + WHI_OFF + (uint32_t)(row * PADK + col) * 2);
        }
#pragma unroll
        for (int ni = 0; ni < 4; ni++) {
            int krow = k0 + (lane & 15);
            LDSM_X2T(b_hi[ni], sbase + XHI_OFF + (uint32_t)(krow * PADC + wn0 + ni * 8) * 2);
        }
#pragma unroll
        for (int mi = 0; mi < 2; mi++)
#pragma unroll
            for (int ni = 0; ni < 4; ni++)
                MMA_F16(acc[mi][ni], a_hi[mi], b_hi[ni]);

        if (isRes) {
            uint32_t a_lo[2][4], b_lo[4][2];
#pragma unroll
            for (int mi = 0; mi < 2; mi++) {
                int row = wm0 + mi * 16 + (lane & 15);
                int col = k0 + (lane >> 4) * 8;
                LDSM_X4(a_lo[mi], sbase + WLO_OFF + (uint32_t)(row * PADK + col) * 2);
            }
#pragma unroll
            for (int ni = 0; ni < 4; ni++) {
                int krow = k0 + (lane & 15);
                LDSM_X2T(b_lo[ni], sbase + XLO_OFF + (uint32_t)(krow * PADC + wn0 + ni * 8) * 2);
            }
#pragma unroll
            for (int mi = 0; mi < 2; mi++)
#pragma unroll
                for (int ni = 0; ni < 4; ni++) {
                    MMA_F16(acc[mi][ni], a_hi[mi], b_lo[ni]);
                    MMA_F16(acc[mi][ni], a_lo[mi], b_hi[ni]);
                }
        }
    }

    if (!isRes) {
        // ---- direct fragment -> g_feat stores (padded tile, 4B-aligned) ----
        size_t tile_base = (size_t)n * COUT * 80 * FS + (size_t)(rg * 25) * FS;
        int crel = rem0 + wn0 + (lane & 3) * 2;    // column within 128-tile -> w/t
#pragma unroll
        for (int mi = 0; mi < 2; mi++) {
            int r = wm0 + mi * 16 + (lane >> 2);   // output channel row o
            float b0 = bias_s[r], b1 = bias_s[r + 8];
            size_t obase0 = tile_base + (size_t)r * (80 * FS);
            size_t obase1 = tile_base + (size_t)(r + 8) * (80 * FS);
#pragma unroll
            for (int ni = 0; ni < 4; ni++) {
                int cl = crel + ni * 8;
                int w = w0, t = cl;
                if (cl >= 300) { w = w0 + 1; t = cl - 300; }
                if (c0 + wn0 + ni * 8 + (lane & 3) * 2 < VT) {
                    __half2 h0 = __floats2half2_rn(acc[mi][ni][0] + b0, acc[mi][ni][1] + b0);
                    __half2 h1 = __floats2half2_rn(acc[mi][ni][2] + b1, acc[mi][ni][3] + b1);
                    *(__half2*)(g_feat + obase0 + (size_t)w * FS + t) = h0;
                    *(__half2*)(g_feat + obase1 + (size_t)w * FS + t) = h1;
                }
            }
        }
    } else {
        __syncthreads();
#pragma unroll
        for (int mi = 0; mi < 2; mi++)
#pragma unroll
            for (int ni = 0; ni < 4; ni++) {
                int r = wm0 + mi * 16 + (lane >> 2);
                int c = wn0 + ni * 8 + (lane & 3) * 2;
                *(float2*)(Cs + r * 132 + c)       = make_float2(acc[mi][ni][0], acc[mi][ni][1]);
                *(float2*)(Cs + (r + 8) * 132 + c) = make_float2(acc[mi][ni][2], acc[mi][ni][3]);
            }
        __syncthreads();

        for (int idx = tid; idx < 128 * 32; idx += 512) {
            int row = idx >> 5, c = (idx & 31) * 4;
            if (c >= ncols) continue;
            float4 v = *(float4*)(Cs + row * 132 + c);
            float b = bias_s[row];
            v.x += b; v.y += b; v.z += b; v.w += b;
            *(float4*)(out + (size_t)(n * COUT + row) * VT + c0 + c) = v;
        }
    }
}

// ---------------------------------------------------------------------------
// kC_m: per (o, n): Out[25 x 300] = A[25 x 75] @ feat[75 x 300] (fp16 mma),
// then bn + residual + relu. feat staging = pure flat uint4 memcpy.
// ---------------------------------------------------------------------------
#define CSd 308
#define KCM_A   (80 * FS * 2)          // 49920
#define KCM_SMEM (KCM_A + 32 * 80 * 2) // 55040
__global__ void __launch_bounds__(256)
kC_m(const float* __restrict__ bn_g, const float* __restrict__ bn_b,
     const float* __restrict__ bn_m, const float* __restrict__ bn_v,
     float* __restrict__ out) {
    extern __shared__ char sm[];
    __half* feat_s = (__half*)sm;           // [80][FS]
    __half* A_s    = (__half*)(sm + KCM_A); // [v 32][k 80]
    float*  Cs     = (float*)sm;            // reuse: [32][CSd]

    int tid = threadIdx.x;
    int wid = tid >> 5, lane = tid & 31;
    int o = blockIdx.x, n = blockIdx.y;

    {
        const uint4* src = (const uint4*)(g_feat + (size_t)(n * COUT + o) * 80 * FS);
        uint4* dst = (uint4*)feat_s;
        for (int idx = tid; idx < 80 * FS * 2 / 16; idx += 256)
            dst[idx] = src[idx];
    }
    for (int idx = tid; idx < 32 * 80; idx += 256) {
        int v = idx / 80, k = idx % 80;
        float av = 0.f;
        if (v < 25 && k < 75) {
            int s = k / 25, w = k % 25;
            av = g_A[(size_t)((s * Nn + n) * COUT + o) * VV + v * 25 + w];
        }
        A_s[v * 80 + k] = __float2half_rn(av);
    }
    __syncthreads();

    uint32_t sb = smem_u32(sm);
    int wn0 = wid * 40;

    float acc[2][5][4];
#pragma unroll
    for (int mi = 0; mi < 2; mi++)
#pragma unroll
        for (int ni = 0; ni < 5; ni++)
#pragma unroll
            for (int q = 0; q < 4; q++) acc[mi][ni][q] = 0.f;

#pragma unroll
    for (int k0 = 0; k0 < 80; k0 += 16) {
        uint32_t a[2][4];
#pragma unroll
        for (int mi = 0; mi < 2; mi++) {
            int row = mi * 16 + (lane & 15);
            int col = k0 + (lane >> 4) * 8;
            LDSM_X4(a[mi], sb + KCM_A + (uint32_t)(row * 80 + col) * 2);
        }
        uint32_t b[5][2];
#pragma unroll
        for (int ni = 0; ni < 5; ni++) {
            int krow = k0 + (lane & 15);
            LDSM_X2T(b[ni], sb + (uint32_t)(krow * FS + wn0 + ni * 8) * 2);
        }
#pragma unroll
        for (int mi = 0; mi < 2; mi++)
#pragma unroll
            for (int ni = 0; ni < 5; ni++)
                MMA_F16(acc[mi][ni], a[mi], b[ni]);
    }

    __syncthreads();

#pragma unroll
    for (int mi = 0; mi < 2; mi++)
#pragma unroll
        for (int ni = 0; ni < 5; ni++) {
            int c = wn0 + ni * 8 + (lane & 3) * 2;
            if (c < 304) {
                int r = mi * 16 + (lane >> 2);
                *(float2*)(Cs + r * CSd + c)       = make_float2(acc[mi][ni][0], acc[mi][ni][1]);
                *(float2*)(Cs + (r + 8) * CSd + c) = make_float2(acc[mi][ni][2], acc[mi][ni][3]);
            }
        }
    __syncthreads();

    float scale = bn_g[o] * rsqrtf(bn_v[o] + EPSf);
    float shift = bn_b[o] - bn_m[o] * scale;
    for (int idx = tid; idx < 25 * 75; idx += 256) {
        int v = idx / 75, t4 = (idx % 75) * 4;
        float4 g = *(float4*)(Cs + v * CSd + t4);
        float* op = out + ((size_t)n * COUT + o) * VT + v * 300 + t4;
        float4 r = *(float4*)op;
        r.x = fmaxf(fmaf(g.x, scale, shift) + r.x, 0.f);
        r.y = fmaxf(fmaf(g.y, scale, shift) + r.y, 0.f);
        r.z = fmaxf(fmaf(g.z, scale, shift) + r.z, 0.f);
        r.w = fmaxf(fmaf(g.w, scale, shift) + r.w, 0.f);
        *(float4*)op = r;
    }
}

// ---------------------------------------------------------------------------
extern "C" void kernel_launch(void* const* d_in, const int* in_sizes, int n_in,
                              void* d_out, int out_size) {
    const float* x       = (const float*)d_in[0];
    const float* ada_A   = (const float*)d_in[1];
    const float* PA      = (const float*)d_in[2];
    const float* conv3_w = (const float*)d_in[3];
    const float* conv3_b = (const float*)d_in[4];
    const float* ada_w   = (const float*)d_in[5];
    const float* ada_b   = (const float*)d_in[6];
    const float* bn_g    = (const float*)d_in[7];
    const float* bn_b    = (const float*)d_in[8];
    const float* bn_m    = (const float*)d_in[9];
    const float* bn_v    = (const float*)d_in[10];
    const float* down_w  = (const float*)d_in[11];
    const float* down_b  = (const float*)d_in[12];
    const float* dbn_g   = (const float*)d_in[13];
    const float* dbn_b   = (const float*)d_in[14];
    const float* dbn_m   = (const float*)d_in[15];
    const float* dbn_v   = (const float*)d_in[16];
    float* out = (float*)d_out;

    cudaFuncSetAttribute(kA,   cudaFuncAttributeMaxDynamicSharedMemorySize, KA_SMEM);
    cudaFuncSetAttribute(kB_m, cudaFuncAttributeMaxDynamicSharedMemorySize, KBM_SMEM);
    cudaFuncSetAttribute(kC_m, cudaFuncAttributeMaxDynamicSharedMemorySize, KCM_SMEM);

    kX<<<(Nn * CIN * VT / 4 + 255) / 256, 256>>>(x);
    kW<<<64, 512>>>(conv3_w, conv3_b, down_w, down_b, dbn_g, dbn_b, dbn_m, dbn_v);
    kA<<<dim3(20, Nn, Ss), 128, KA_SMEM>>>(ada_A, PA, ada_w, ada_b);
    kB_m<<<dim3(59, 4, Nn), 512, KBM_SMEM>>>(out);
    kC_m<<<dim3(COUT, Nn), 256, KCM_SMEM>>>(bn_g, bn_b, bn_m, bn_v, out);
}

// round 14
// speedup vs baseline: 1.0942x; 1.0942x over previous
#include <cuda_runtime.h>
#include <cuda_fp16.h>
#include <cuda_bf16.h>
#include <cstdint>

#define Nn   32
#define CIN  64
#define COUT 128
#define Vv   25
#define Tlen 300
#define Ss   3
#define VT   7500
#define VV   625
#define EPSf 1e-5f
#define FS   312   // padded feat row length (halves)

typedef unsigned long long u64;

// ---- device scratch (allocation-free) ----
// g_feat: [n][o][80 rows (s*25+w)][FS cols (t)] fp16 padded tile; pad rows/cols
//         never written -> stay zero (static init).
// g_Ah:   [n][o][32 rows (v)][80 cols (s*25+w)] fp16 padded tile; same deal.
__device__ __align__(16) __half g_feat[(size_t)Nn * COUT * 80 * FS];  // 204 MB
__device__ __align__(16) __half g_Ah[(size_t)Nn * COUT * 32 * 80];    // 21 MB
__device__ __align__(16) __half g_Xhi[Nn * CIN * VT];
__device__ __align__(16) __half g_Xlo[Nn * CIN * VT];
__device__ __align__(16) __half g_Whi[512 * 64];
__device__ __align__(16) __half g_Wlo[512 * 64];
__device__ __align__(16) float g_bias[512];

// ---- scalar/FMA2 helpers ----
__device__ __forceinline__ void fma2(u64& d, u64 a, u64 b) {
    asm("fma.rn.f32x2 %0, %1, %2, %0;" : "+l"(d) : "l"(a), "l"(b));
}
__device__ __forceinline__ u64 dup2(float v) {
    u64 r; asm("mov.b64 %0, {%1, %1};" : "=l"(r) : "f"(v)); return r;
}
__device__ __forceinline__ u64 pack2(float lo, float hi) {
    u64 r; asm("mov.b64 %0, {%1, %2};" : "=l"(r) : "f"(lo), "f"(hi)); return r;
}
__device__ __forceinline__ float lo32(u64 v) { return __uint_as_float((unsigned)v); }
__device__ __forceinline__ float hi32(u64 v) { return __uint_as_float((unsigned)(v >> 32)); }

__device__ __forceinline__ uint32_t smem_u32(const void* p) {
    uint32_t a;
    asm("{ .reg .u64 t; cvta.to.shared.u64 t, %1; cvt.u32.u64 %0, t; }" : "=r"(a) : "l"(p));
    return a;
}

// ---- mma.sync / ldmatrix ----
#define LDSM_X4(r, addr) \
    asm volatile("ldmatrix.sync.aligned.m8n8.x4.shared.b16 {%0,%1,%2,%3}, [%4];" \
        : "=r"((r)[0]), "=r"((r)[1]), "=r"((r)[2]), "=r"((r)[3]) : "r"(addr))
#define LDSM_X2T(r, addr) \
    asm volatile("ldmatrix.sync.aligned.m8n8.x2.trans.shared.b16 {%0,%1}, [%2];" \
        : "=r"((r)[0]), "=r"((r)[1]) : "r"(addr))
#define MMA_F16(d, a, b) \
    asm volatile("mma.sync.aligned.m16n8k16.row.col.f32.f16.f16.f32 " \
        "{%0,%1,%2,%3}, {%4,%5,%6,%7}, {%8,%9}, {%0,%1,%2,%3};" \
        : "+f"((d)[0]), "+f"((d)[1]), "+f"((d)[2]), "+f"((d)[3]) \
        : "r"((a)[0]), "r"((a)[1]), "r"((a)[2]), "r"((a)[3]), "r"((b)[0]), "r"((b)[1]))

// ---------------------------------------------------------------------------
// kX: pre-split x (fp32) into fp16 hi/lo, linear layout identical to x.
// ---------------------------------------------------------------------------
__global__ void kX(const float* __restrict__ x) {
    size_t i4 = ((size_t)blockIdx.x * blockDim.x + threadIdx.x) * 4;
    if (i4 >= (size_t)Nn * CIN * VT) return;
    float4 v = *(const float4*)(x + i4);
    __half h0 = __float2half_rn(v.x), h1 = __float2half_rn(v.y);
    __half h2 = __float2half_rn(v.z), h3 = __float2half_rn(v.w);
    __half2 p0(h0, h1), p1(h2, h3);
    uint2 ph; ph.x = *(unsigned*)&p0; ph.y = *(unsigned*)&p1;
    *(uint2*)(g_Xhi + i4) = ph;
    __half2 q0(__float2half_rn(v.x - __half2float(h0)), __float2half_rn(v.y - __half2float(h1)));
    __half2 q1(__float2half_rn(v.z - __half2float(h2)), __float2half_rn(v.w - __half2float(h3)));
    uint2 pl; pl.x = *(unsigned*)&q0; pl.y = *(unsigned*)&q1;
    *(uint2*)(g_Xlo + i4) = pl;
}

// ---------------------------------------------------------------------------
// kW: split folded W into fp16 hi/lo + bias
// ---------------------------------------------------------------------------
__global__ void kW(const float* __restrict__ conv3_w, const float* __restrict__ conv3_b,
                   const float* __restrict__ down_w,  const float* __restrict__ down_b,
                   const float* __restrict__ dg, const float* __restrict__ dbeta,
                   const float* __restrict__ dm, const float* __restrict__ dvar) {
    int idx = blockIdx.x * blockDim.x + threadIdx.x;
    if (idx >= 512 * 64) return;
    int r = idx >> 6, k = idx & 63;
    float w;
    if (r < Ss * COUT) {
        w = conv3_w[r * CIN + k];
    } else {
        int o = r - Ss * COUT;
        w = dg[o] * rsqrtf(dvar[o] + EPSf) * down_w[o * CIN + k];
    }
    __half hi = __float2half_rn(w);
    g_Whi[idx] = hi;
    g_Wlo[idx] = __float2half_rn(w - __half2float(hi));
    if (k == 0) {
        float b;
        if (r < Ss * COUT) b = conv3_b[r];
        else {
            int o = r - Ss * COUT;
            float sc = dg[o] * rsqrtf(dvar[o] + EPSf);
            b = sc * (down_b[o] - dm[o]) + dbeta[o];
        }
        g_bias[r] = b;
    }
}

// ---------------------------------------------------------------------------
// kA: g_Ah[n][o][v][s*25+w] = fp16((ada_w . ada_A + ada_b) * PA).
// grid (20 = 5 vw-chunks x 4 o-groups, n, s), 128 threads, FMA2.
// ---------------------------------------------------------------------------
#define KA_SMEM (64 * 16 * 8 + 64 * 125 * 4 + 32 * 4)
__global__ void __launch_bounds__(128)
kA(const float* __restrict__ adaA, const float* __restrict__ PA,
   const float* __restrict__ ada_w, const float* __restrict__ ada_b) {
    extern __shared__ char smA[];
    u64*   Wp  = (u64*)smA;
    float* Xa  = (float*)(smA + 64 * 16 * 8);
    float* bsm = (float*)(smA + 64 * 16 * 8 + 64 * 125 * 4);

    int tid = threadIdx.x;
    int s = blockIdx.z, n = blockIdx.y;
    int g = blockIdx.x & 3;
    int vw0 = (blockIdx.x >> 2) * 125;

    const float* wsrc = ada_w + s * COUT * CIN + g * 32 * CIN;
    for (int idx = tid; idx < 64 * 16; idx += 128) {
        int i = idx >> 4, op = idx & 15;
        Wp[i * 16 + op] = pack2(wsrc[(2 * op) * CIN + i], wsrc[(2 * op + 1) * CIN + i]);
    }
    for (int idx = tid; idx < 64 * 125; idx += 128) {
        int i = idx / 125, j = idx % 125;
        Xa[i * 125 + j] = adaA[(size_t)(n * CIN + i) * VV + vw0 + j];
    }
    if (tid < 32) bsm[tid] = ada_b[s * COUT + g * 32 + tid];
    __syncthreads();
    if (tid >= 125) return;

    int vw = vw0 + tid;
    int v = vw / 25, w = vw - v * 25;
    float pa = PA[s * VV + vw];

    u64 acc[16];
#pragma unroll
    for (int p = 0; p < 16; p++) acc[p] = 0ull;

#pragma unroll 8
    for (int i = 0; i < CIN; i++) {
        u64 f2 = dup2(Xa[i * 125 + tid]);
        const ulonglong2* wr = (const ulonglong2*)(Wp + i * 16);
#pragma unroll
        for (int p = 0; p < 8; p++) {
            ulonglong2 wv = wr[p];
            fma2(acc[2 * p],     wv.x, f2);
            fma2(acc[2 * p + 1], wv.y, f2);
        }
    }
    // write fp16 into padded [32][80] tile for (n, o)
    __half* outp = g_Ah + ((size_t)(n * COUT + g * 32) * 32 + v) * 80 + s * 25 + w;
#pragma unroll
    for (int p = 0; p < 16; p++) {
        outp[(size_t)(2 * p) * (32 * 80)]     = __float2half_rn((lo32(acc[p]) + bsm[2 * p])     * pa);
        outp[(size_t)(2 * p + 1) * (32 * 80)] = __float2half_rn((hi32(acc[p]) + bsm[2 * p + 1]) * pa);
    }
}

// ---------------------------------------------------------------------------
// kB_m: tensor GEMM C[128r x 128c] = W[128x64] @ X[64 x 128c].  (R12 version)
// feat rows -> padded g_feat tiles via Cs smem epilogue; res rows -> d_out.
// grid (59, 4, 32), 512 threads, 2 CTAs/SM.
// ---------------------------------------------------------------------------
#define PADK 72
#define PADC 136
#define WHI_OFF 0
#define WLO_OFF (128 * PADK * 2)
#define XHI_OFF (WLO_OFF + 128 * PADK * 2)
#define XLO_OFF (XHI_OFF + 64 * PADC * 2)
#define BIAS_OFF (XLO_OFF + 64 * PADC * 2)
#define KBM_SMEM (BIAS_OFF + 128 * 4)
__global__ void __launch_bounds__(512, 2)
kB_m(float* __restrict__ out) {
    extern __shared__ char sm[];
    __half* Whi_s = (__half*)(sm + WHI_OFF);
    __half* Wlo_s = (__half*)(sm + WLO_OFF);
    __half* Xhi_s = (__half*)(sm + XHI_OFF);
    __half* Xlo_s = (__half*)(sm + XLO_OFF);
    float* bias_s = (float*)(sm + BIAS_OFF);
    float* Cs = (float*)sm;

    int tid = threadIdx.x;
    int wid = tid >> 5, lane = tid & 31;
    int n = blockIdx.z, rg = blockIdx.y;
    int c0 = blockIdx.x * 128;
    int r0 = rg * 128;
    int ncols = VT - c0; if (ncols > 128) ncols = 128;
    bool isRes = (rg == 3);
    int w0 = c0 / 300;
    int rem0 = c0 - w0 * 300;

    for (int idx = tid; idx < 1024; idx += 512) {
        int row = idx >> 3, kc = (idx & 7) * 8;
        uint4 v = *(const uint4*)(g_Whi + (size_t)(r0 + row) * 64 + kc);
        *(uint4*)(Whi_s + row * PADK + kc) = v;
    }
    if (isRes) {
        for (int idx = tid; idx < 1024; idx += 512) {
            int row = idx >> 3, kc = (idx & 7) * 8;
            uint4 v = *(const uint4*)(g_Wlo + (size_t)(r0 + row) * 64 + kc);
            *(uint4*)(Wlo_s + row * PADK + kc) = v;
        }
    }
    if (tid < 128) bias_s[tid] = g_bias[r0 + tid];

    for (int idx = tid; idx < 64 * 32; idx += 512) {
        int k = idx >> 5, c4 = (idx & 31) << 2;
        uint2 v = make_uint2(0u, 0u);
        if (c4 < ncols) v = *(const uint2*)(g_Xhi + (size_t)(n * CIN + k) * VT + c0 + c4);
        *(uint2*)(Xhi_s + k * PADC + c4) = v;
        if (isRes) {
            uint2 vl = make_uint2(0u, 0u);
            if (c4 < ncols) vl = *(const uint2*)(g_Xlo + (size_t)(n * CIN + k) * VT + c0 + c4);
            *(uint2*)(Xlo_s + k * PADC + c4) = vl;
        }
    }
    __syncthreads();

    int wm0 = (wid & 3) * 32;
    int wn0 = (wid >> 2) * 32;
    uint32_t sbase = smem_u32(sm);

    float acc[2][4][4];
#pragma unroll
    for (int mi = 0; mi < 2; mi++)
#pragma unroll
        for (int ni = 0; ni < 4; ni++)
#pragma unroll
            for (int q = 0; q < 4; q++) acc[mi][ni][q] = 0.f;

#pragma unroll
    for (int k0 = 0; k0 < 64; k0 += 16) {
        uint32_t a_hi[2][4], b_hi[4][2];
#pragma unroll
        for (int mi = 0; mi < 2; mi++) {
            int row = wm0 + mi * 16 + (lane & 15);
            int col = k0 + (lane >> 4) * 8;
            LDSM_X4(a_hi[mi], sbase + WHI_OFF + (uint32_t)(row * PADK + col) * 2);
        }
#pragma unroll
        for (int ni = 0; ni < 4; ni++) {
            int krow = k0 + (lane & 15);
            LDSM_X2T(b_hi[ni], sbase + XHI_OFF + (uint32_t)(krow * PADC + wn0 + ni * 8) * 2);
        }
#pragma unroll
        for (int mi = 0; mi < 2; mi++)
#pragma unroll
            for (int ni = 0; ni < 4; ni++)
                MMA_F16(acc[mi][ni], a_hi[mi], b_hi[ni]);

        if (isRes) {
            uint32_t a_lo[2][4], b_lo[4][2];
#pragma unroll
            for (int mi = 0; mi < 2; mi++) {
                int row = wm0 + mi * 16 + (lane & 15);
                int col = k0 + (lane >> 4) * 8;
                LDSM_X4(a_lo[mi], sbase + WLO_OFF + (uint32_t)(row * PADK + col) * 2);
            }
#pragma unroll
            for (int ni = 0; ni < 4; ni++) {
                int krow = k0 + (lane & 15);
                LDSM_X2T(b_lo[ni], sbase + XLO_OFF + (uint32_t)(krow * PADC + wn0 + ni * 8) * 2);
            }
#pragma unroll
            for (int mi = 0; mi < 2; mi++)
#pragma unroll
                for (int ni = 0; ni < 4; ni++) {
                    MMA_F16(acc[mi][ni], a_hi[mi], b_lo[ni]);
                    MMA_F16(acc[mi][ni], a_lo[mi], b_hi[ni]);
                }
        }
    }

    __syncthreads();

#pragma unroll
    for (int mi = 0; mi < 2; mi++)
#pragma unroll
        for (int ni = 0; ni < 4; ni++) {
            int r = wm0 + mi * 16 + (lane >> 2);
            int c = wn0 + ni * 8 + (lane & 3) * 2;
            *(float2*)(Cs + r * 132 + c)       = make_float2(acc[mi][ni][0], acc[mi][ni][1]);
            *(float2*)(Cs + (r + 8) * 132 + c) = make_float2(acc[mi][ni][2], acc[mi][ni][3]);
        }
    __syncthreads();

    for (int idx = tid; idx < 128 * 32; idx += 512) {
        int row = idx >> 5, c = (idx & 31) * 4;
        if (c >= ncols) continue;
        float4 v = *(float4*)(Cs + row * 132 + c);
        float b = bias_s[row];
        v.x += b; v.y += b; v.z += b; v.w += b;
        if (!isRes) {
            __half2 h0 = __floats2half2_rn(v.x, v.y);
            __half2 h1 = __floats2half2_rn(v.z, v.w);
            uint2 pk; pk.x = *(unsigned*)&h0; pk.y = *(unsigned*)&h1;
            int cl = rem0 + c;
            int w = w0, t = cl;
            if (cl >= 300) { w = w0 + 1; t = cl - 300; }
            *(uint2*)(g_feat + ((size_t)(n * COUT + row) * 80 + rg * 25 + w) * FS + t) = pk;
        } else {
            *(float4*)(out + (size_t)(n * COUT + row) * VT + c0 + c) = v;
        }
    }
}

// ---------------------------------------------------------------------------
// kC_m: per (o, n): Out[25 x 300] = A[25 x 75] @ feat[75 x 300] (fp16 mma),
// then bn + residual + relu. BOTH stagings are flat uint4 memcpys.
// ---------------------------------------------------------------------------
#define CSd 308
#define KCM_A   (80 * FS * 2)          // 49920
#define KCM_SMEM (KCM_A + 32 * 80 * 2) // 55040
__global__ void __launch_bounds__(256)
kC_m(const float* __restrict__ bn_g, const float* __restrict__ bn_b,
     const float* __restrict__ bn_m, const float* __restrict__ bn_v,
     float* __restrict__ out) {
    extern __shared__ char sm[];
    __half* feat_s = (__half*)sm;           // [80][FS]
    __half* A_s    = (__half*)(sm + KCM_A); // [32][80]
    float*  Cs     = (float*)sm;            // reuse: [32][CSd]

    int tid = threadIdx.x;
    int wid = tid >> 5, lane = tid & 31;
    int o = blockIdx.x, n = blockIdx.y;

    // ---- stage feat: flat uint4 copy ----
    {
        const uint4* src = (const uint4*)(g_feat + (size_t)(n * COUT + o) * 80 * FS);
        uint4* dst = (uint4*)feat_s;
        for (int idx = tid; idx < 80 * FS * 2 / 16; idx += 256)
            dst[idx] = src[idx];
    }
    // ---- stage A: flat uint4 copy (320 chunks) ----
    {
        const uint4* src = (const uint4*)(g_Ah + (size_t)(n * COUT + o) * 32 * 80);
        uint4* dst = (uint4*)A_s;
        for (int idx = tid; idx < 32 * 80 * 2 / 16; idx += 256)
            dst[idx] = src[idx];
    }
    __syncthreads();

    uint32_t sb = smem_u32(sm);
    int wn0 = wid * 40;

    float acc[2][5][4];
#pragma unroll
    for (int mi = 0; mi < 2; mi++)
#pragma unroll
        for (int ni = 0; ni < 5; ni++)
#pragma unroll
            for (int q = 0; q < 4; q++) acc[mi][ni][q] = 0.f;

#pragma unroll
    for (int k0 = 0; k0 < 80; k0 += 16) {
        uint32_t a[2][4];
#pragma unroll
        for (int mi = 0; mi < 2; mi++) {
            int row = mi * 16 + (lane & 15);
            int col = k0 + (lane >> 4) * 8;
            LDSM_X4(a[mi], sb + KCM_A + (uint32_t)(row * 80 + col) * 2);
        }
        uint32_t b[5][2];
#pragma unroll
        for (int ni = 0; ni < 5; ni++) {
            int krow = k0 + (lane & 15);
            LDSM_X2T(b[ni], sb + (uint32_t)(krow * FS + wn0 + ni * 8) * 2);
        }
#pragma unroll
        for (int mi = 0; mi < 2; mi++)
#pragma unroll
            for (int ni = 0; ni < 5; ni++)
                MMA_F16(acc[mi][ni], a[mi], b[ni]);
    }

    __syncthreads();

#pragma unroll
    for (int mi = 0; mi < 2; mi++)
#pragma unroll
        for (int ni = 0; ni < 5; ni++) {
            int c = wn0 + ni * 8 + (lane & 3) * 2;
            if (c < 304) {
                int r = mi * 16 + (lane >> 2);
                *(float2*)(Cs + r * CSd + c)       = make_float2(acc[mi][ni][0], acc[mi][ni][1]);
                *(float2*)(Cs + (r + 8) * CSd + c) = make_float2(acc[mi][ni][2], acc[mi][ni][3]);
            }
        }
    __syncthreads();

    float scale = bn_g[o] * rsqrtf(bn_v[o] + EPSf);
    float shift = bn_b[o] - bn_m[o] * scale;
    for (int idx = tid; idx < 25 * 75; idx += 256) {
        int v = idx / 75, t4 = (idx % 75) * 4;
        float4 g = *(float4*)(Cs + v * CSd + t4);
        float* op = out + ((size_t)n * COUT + o) * VT + v * 300 + t4;
        float4 r = *(float4*)op;
        r.x = fmaxf(fmaf(g.x, scale, shift) + r.x, 0.f);
        r.y = fmaxf(fmaf(g.y, scale, shift) + r.y, 0.f);
        r.z = fmaxf(fmaf(g.z, scale, shift) + r.z, 0.f);
        r.w = fmaxf(fmaf(g.w, scale, shift) + r.w, 0.f);
        *(float4*)op = r;
    }
}

// ---------------------------------------------------------------------------
extern "C" void kernel_launch(void* const* d_in, const int* in_sizes, int n_in,
                              void* d_out, int out_size) {
    const float* x       = (const float*)d_in[0];
    const float* ada_A   = (const float*)d_in[1];
    const float* PA      = (const float*)d_in[2];
    const float* conv3_w = (const float*)d_in[3];
    const float* conv3_b = (const float*)d_in[4];
    const float* ada_w   = (const float*)d_in[5];
    const float* ada_b   = (const float*)d_in[6];
    const float* bn_g    = (const float*)d_in[7];
    const float* bn_b    = (const float*)d_in[8];
    const float* bn_m    = (const float*)d_in[9];
    const float* bn_v    = (const float*)d_in[10];
    const float* down_w  = (const float*)d_in[11];
    const float* down_b  = (const float*)d_in[12];
    const float* dbn_g   = (const float*)d_in[13];
    const float* dbn_b   = (const float*)d_in[14];
    const float* dbn_m   = (const float*)d_in[15];
    const float* dbn_v   = (const float*)d_in[16];
    float* out = (float*)d_out;

    cudaFuncSetAttribute(kA,   cudaFuncAttributeMaxDynamicSharedMemorySize, KA_SMEM);
    cudaFuncSetAttribute(kB_m, cudaFuncAttributeMaxDynamicSharedMemorySize, KBM_SMEM);
    cudaFuncSetAttribute(kC_m, cudaFuncAttributeMaxDynamicSharedMemorySize, KCM_SMEM);

    kX<<<(Nn * CIN * VT / 4 + 255) / 256, 256>>>(x);
    kW<<<64, 512>>>(conv3_w, conv3_b, down_w, down_b, dbn_g, dbn_b, dbn_m, dbn_v);
    kA<<<dim3(20, Nn, Ss), 128, KA_SMEM>>>(ada_A, PA, ada_w, ada_b);
    kB_m<<<dim3(59, 4, Nn), 512, KBM_SMEM>>>(out);
    kC_m<<<dim3(COUT, Nn), 256, KCM_SMEM>>>(bn_g, bn_b, bn_m, bn_v, out);
}

// round 15
// speedup vs baseline: 1.3681x; 1.2503x over previous
#include <cuda_runtime.h>
#include <cuda_fp16.h>
#include <cuda_bf16.h>
#include <cstdint>

#define Nn   32
#define CIN  64
#define COUT 128
#define Vv   25
#define Tlen 300
#define Ss   3
#define VT   7500
#define VV   625
#define EPSf 1e-5f
#define FS   312   // padded feat row length (halves)

typedef unsigned long long u64;

// ---- device scratch (allocation-free) ----
__device__ __align__(16) __half g_feat[(size_t)Nn * COUT * 80 * FS];  // 204 MB
__device__ __align__(16) __half g_Ah[(size_t)Nn * COUT * 32 * 80];    // 21 MB
__device__ __align__(16) __half g_Xhi[Nn * CIN * VT];
__device__ __align__(16) __half g_Xlo[Nn * CIN * VT];
__device__ __align__(16) __half g_Whi[512 * 64];
__device__ __align__(16) __half g_Wlo[512 * 64];
__device__ __align__(16) float g_bias[512];

// ---- scalar/FMA2 helpers ----
__device__ __forceinline__ void fma2(u64& d, u64 a, u64 b) {
    asm("fma.rn.f32x2 %0, %1, %2, %0;" : "+l"(d) : "l"(a), "l"(b));
}
__device__ __forceinline__ u64 dup2(float v) {
    u64 r; asm("mov.b64 %0, {%1, %1};" : "=l"(r) : "f"(v)); return r;
}
__device__ __forceinline__ u64 pack2(float lo, float hi) {
    u64 r; asm("mov.b64 %0, {%1, %2};" : "=l"(r) : "f"(lo), "f"(hi)); return r;
}
__device__ __forceinline__ float lo32(u64 v) { return __uint_as_float((unsigned)v); }
__device__ __forceinline__ float hi32(u64 v) { return __uint_as_float((unsigned)(v >> 32)); }

__device__ __forceinline__ uint32_t smem_u32(const void* p) {
    uint32_t a;
    asm("{ .reg .u64 t; cvta.to.shared.u64 t, %1; cvt.u32.u64 %0, t; }" : "=r"(a) : "l"(p));
    return a;
}

// ---- cp.async (sm_80+) ----
__device__ __forceinline__ void cp16(uint32_t dst, const void* src) {
    asm volatile("cp.async.cg.shared.global [%0], [%1], 16;" :: "r"(dst), "l"(src));
}
__device__ __forceinline__ void cp8z(uint32_t dst, const void* src, bool pred) {
    int sz = pred ? 8 : 0;
    asm volatile("cp.async.ca.shared.global [%0], [%1], 8, %2;"
                 :: "r"(dst), "l"(src), "r"(sz));
}
#define CP_COMMIT() asm volatile("cp.async.commit_group;" ::: "memory")
#define CP_WAIT0()  asm volatile("cp.async.wait_group 0;" ::: "memory")

// ---- mma.sync / ldmatrix ----
#define LDSM_X4(r, addr) \
    asm volatile("ldmatrix.sync.aligned.m8n8.x4.shared.b16 {%0,%1,%2,%3}, [%4];" \
        : "=r"((r)[0]), "=r"((r)[1]), "=r"((r)[2]), "=r"((r)[3]) : "r"(addr))
#define LDSM_X2T(r, addr) \
    asm volatile("ldmatrix.sync.aligned.m8n8.x2.trans.shared.b16 {%0,%1}, [%2];" \
        : "=r"((r)[0]), "=r"((r)[1]) : "r"(addr))
#define MMA_F16(d, a, b) \
    asm volatile("mma.sync.aligned.m16n8k16.row.col.f32.f16.f16.f32 " \
        "{%0,%1,%2,%3}, {%4,%5,%6,%7}, {%8,%9}, {%0,%1,%2,%3};" \
        : "+f"((d)[0]), "+f"((d)[1]), "+f"((d)[2]), "+f"((d)[3]) \
        : "r"((a)[0]), "r"((a)[1]), "r"((a)[2]), "r"((a)[3]), "r"((b)[0]), "r"((b)[1]))

// ---------------------------------------------------------------------------
// kX: pre-split x (fp32) into fp16 hi/lo.
// ---------------------------------------------------------------------------
__global__ void kX(const float* __restrict__ x) {
    size_t i4 = ((size_t)blockIdx.x * blockDim.x + threadIdx.x) * 4;
    if (i4 >= (size_t)Nn * CIN * VT) return;
    float4 v = *(const float4*)(x + i4);
    __half h0 = __float2half_rn(v.x), h1 = __float2half_rn(v.y);
    __half h2 = __float2half_rn(v.z), h3 = __float2half_rn(v.w);
    __half2 p0(h0, h1), p1(h2, h3);
    uint2 ph; ph.x = *(unsigned*)&p0; ph.y = *(unsigned*)&p1;
    *(uint2*)(g_Xhi + i4) = ph;
    __half2 q0(__float2half_rn(v.x - __half2float(h0)), __float2half_rn(v.y - __half2float(h1)));
    __half2 q1(__float2half_rn(v.z - __half2float(h2)), __float2half_rn(v.w - __half2float(h3)));
    uint2 pl; pl.x = *(unsigned*)&q0; pl.y = *(unsigned*)&q1;
    *(uint2*)(g_Xlo + i4) = pl;
}

// ---------------------------------------------------------------------------
// kW: split folded W into fp16 hi/lo + bias
// ---------------------------------------------------------------------------
__global__ void kW(const float* __restrict__ conv3_w, const float* __restrict__ conv3_b,
                   const float* __restrict__ down_w,  const float* __restrict__ down_b,
                   const float* __restrict__ dg, const float* __restrict__ dbeta,
                   const float* __restrict__ dm, const float* __restrict__ dvar) {
    int idx = blockIdx.x * blockDim.x + threadIdx.x;
    if (idx >= 512 * 64) return;
    int r = idx >> 6, k = idx & 63;
    float w;
    if (r < Ss * COUT) {
        w = conv3_w[r * CIN + k];
    } else {
        int o = r - Ss * COUT;
        w = dg[o] * rsqrtf(dvar[o] + EPSf) * down_w[o * CIN + k];
    }
    __half hi = __float2half_rn(w);
    g_Whi[idx] = hi;
    g_Wlo[idx] = __float2half_rn(w - __half2float(hi));
    if (k == 0) {
        float b;
        if (r < Ss * COUT) b = conv3_b[r];
        else {
            int o = r - Ss * COUT;
            float sc = dg[o] * rsqrtf(dvar[o] + EPSf);
            b = sc * (down_b[o] - dm[o]) + dbeta[o];
        }
        g_bias[r] = b;
    }
}

// ---------------------------------------------------------------------------
// kA: g_Ah[n][o][v][s*25+w] = fp16((ada_w . ada_A + ada_b) * PA).
// ---------------------------------------------------------------------------
#define KA_SMEM (64 * 16 * 8 + 64 * 125 * 4 + 32 * 4)
__global__ void __launch_bounds__(128)
kA(const float* __restrict__ adaA, const float* __restrict__ PA,
   const float* __restrict__ ada_w, const float* __restrict__ ada_b) {
    extern __shared__ char smA[];
    u64*   Wp  = (u64*)smA;
    float* Xa  = (float*)(smA + 64 * 16 * 8);
    float* bsm = (float*)(smA + 64 * 16 * 8 + 64 * 125 * 4);

    int tid = threadIdx.x;
    int s = blockIdx.z, n = blockIdx.y;
    int g = blockIdx.x & 3;
    int vw0 = (blockIdx.x >> 2) * 125;

    const float* wsrc = ada_w + s * COUT * CIN + g * 32 * CIN;
    for (int idx = tid; idx < 64 * 16; idx += 128) {
        int i = idx >> 4, op = idx & 15;
        Wp[i * 16 + op] = pack2(wsrc[(2 * op) * CIN + i], wsrc[(2 * op + 1) * CIN + i]);
    }
    for (int idx = tid; idx < 64 * 125; idx += 128) {
        int i = idx / 125, j = idx % 125;
        Xa[i * 125 + j] = adaA[(size_t)(n * CIN + i) * VV + vw0 + j];
    }
    if (tid < 32) bsm[tid] = ada_b[s * COUT + g * 32 + tid];
    __syncthreads();
    if (tid >= 125) return;

    int vw = vw0 + tid;
    int v = vw / 25, w = vw - v * 25;
    float pa = PA[s * VV + vw];

    u64 acc[16];
#pragma unroll
    for (int p = 0; p < 16; p++) acc[p] = 0ull;

#pragma unroll 8
    for (int i = 0; i < CIN; i++) {
        u64 f2 = dup2(Xa[i * 125 + tid]);
        const ulonglong2* wr = (const ulonglong2*)(Wp + i * 16);
#pragma unroll
        for (int p = 0; p < 8; p++) {
            ulonglong2 wv = wr[p];
            fma2(acc[2 * p],     wv.x, f2);
            fma2(acc[2 * p + 1], wv.y, f2);
        }
    }
    __half* outp = g_Ah + ((size_t)(n * COUT + g * 32) * 32 + v) * 80 + s * 25 + w;
#pragma unroll
    for (int p = 0; p < 16; p++) {
        outp[(size_t)(2 * p) * (32 * 80)]     = __float2half_rn((lo32(acc[p]) + bsm[2 * p])     * pa);
        outp[(size_t)(2 * p + 1) * (32 * 80)] = __float2half_rn((hi32(acc[p]) + bsm[2 * p + 1]) * pa);
    }
}

// ---------------------------------------------------------------------------
// kB_m: tensor GEMM C[128r x 128c] = W[128x64] @ X[64 x 128c].
// Staging via cp.async. grid (59, 4, 32), 512 threads, 2 CTAs/SM.
// ---------------------------------------------------------------------------
#define PADK 72
#define PADC 136
#define WHI_OFF 0
#define WLO_OFF (128 * PADK * 2)
#define XHI_OFF (WLO_OFF + 128 * PADK * 2)
#define XLO_OFF (XHI_OFF + 64 * PADC * 2)
#define BIAS_OFF (XLO_OFF + 64 * PADC * 2)
#define KBM_SMEM (BIAS_OFF + 128 * 4)
__global__ void __launch_bounds__(512, 2)
kB_m(float* __restrict__ out) {
    extern __shared__ char sm[];
    float* bias_s = (float*)(sm + BIAS_OFF);
    float* Cs = (float*)sm;

    int tid = threadIdx.x;
    int wid = tid >> 5, lane = tid & 31;
    int n = blockIdx.z, rg = blockIdx.y;
    int c0 = blockIdx.x * 128;
    int r0 = rg * 128;
    int ncols = VT - c0; if (ncols > 128) ncols = 128;
    bool isRes = (rg == 3);
    int w0 = c0 / 300;
    int rem0 = c0 - w0 * 300;
    uint32_t sbase = smem_u32(sm);

    // ---- stage W (cp16; 1024 chunks hi, +1024 lo for res) ----
    for (int idx = tid; idx < 1024; idx += 512) {
        int row = idx >> 3, kc = (idx & 7) * 8;
        cp16(sbase + WHI_OFF + (uint32_t)(row * PADK + kc) * 2,
             g_Whi + (size_t)(r0 + row) * 64 + kc);
    }
    if (isRes) {
        for (int idx = tid; idx < 1024; idx += 512) {
            int row = idx >> 3, kc = (idx & 7) * 8;
            cp16(sbase + WLO_OFF + (uint32_t)(row * PADK + kc) * 2,
                 g_Wlo + (size_t)(r0 + row) * 64 + kc);
        }
    }
    if (tid < 128) bias_s[tid] = g_bias[r0 + tid];

    // ---- stage X (cp8 with zfill on edge tile) ----
    for (int idx = tid; idx < 64 * 32; idx += 512) {
        int k = idx >> 5, c4 = (idx & 31) << 2;
        bool ok = (c4 < ncols);
        const __half* src = g_Xhi + (size_t)(n * CIN + k) * VT + c0 + (ok ? c4 : 0);
        cp8z(sbase + XHI_OFF + (uint32_t)(k * PADC + c4) * 2, src, ok);
        if (isRes) {
            const __half* srcl = g_Xlo + (size_t)(n * CIN + k) * VT + c0 + (ok ? c4 : 0);
            cp8z(sbase + XLO_OFF + (uint32_t)(k * PADC + c4) * 2, srcl, ok);
        }
    }
    CP_COMMIT();
    CP_WAIT0();
    __syncthreads();

    int wm0 = (wid & 3) * 32;
    int wn0 = (wid >> 2) * 32;

    float acc[2][4][4];
#pragma unroll
    for (int mi = 0; mi < 2; mi++)
#pragma unroll
        for (int ni = 0; ni < 4; ni++)
#pragma unroll
            for (int q = 0; q < 4; q++) acc[mi][ni][q] = 0.f;

#pragma unroll
    for (int k0 = 0; k0 < 64; k0 += 16) {
        uint32_t a_hi[2][4], b_hi[4][2];
#pragma unroll
        for (int mi = 0; mi < 2; mi++) {
            int row = wm0 + mi * 16 + (lane & 15);
            int col = k0 + (lane >> 4) * 8;
            LDSM_X4(a_hi[mi], sbase + WHI_OFF + (uint32_t)(row * PADK + col) * 2);
        }
#pragma unroll
        for (int ni = 0; ni < 4; ni++) {
            int krow = k0 + (lane & 15);
            LDSM_X2T(b_hi[ni], sbase + XHI_OFF + (uint32_t)(krow * PADC + wn0 + ni * 8) * 2);
        }
#pragma unroll
        for (int mi = 0; mi < 2; mi++)
#pragma unroll
            for (int ni = 0; ni < 4; ni++)
                MMA_F16(acc[mi][ni], a_hi[mi], b_hi[ni]);

        if (isRes) {
            uint32_t a_lo[2][4], b_lo[4][2];
#pragma unroll
            for (int mi = 0; mi < 2; mi++) {
                int row = wm0 + mi * 16 + (lane & 15);
                int col = k0 + (lane >> 4) * 8;
                LDSM_X4(a_lo[mi], sbase + WLO_OFF + (uint32_t)(row * PADK + col) * 2);
            }
#pragma unroll
            for (int ni = 0; ni < 4; ni++) {
                int krow = k0 + (lane & 15);
                LDSM_X2T(b_lo[ni], sbase + XLO_OFF + (uint32_t)(krow * PADC + wn0 + ni * 8) * 2);
            }
#pragma unroll
            for (int mi = 0; mi < 2; mi++)
#pragma unroll
                for (int ni = 0; ni < 4; ni++) {
                    MMA_F16(acc[mi][ni], a_hi[mi], b_lo[ni]);
                    MMA_F16(acc[mi][ni], a_lo[mi], b_hi[ni]);
                }
        }
    }

    __syncthreads();

#pragma unroll
    for (int mi = 0; mi < 2; mi++)
#pragma unroll
        for (int ni = 0; ni < 4; ni++) {
            int r = wm0 + mi * 16 + (lane >> 2);
            int c = wn0 + ni * 8 + (lane & 3) * 2;
            *(float2*)(Cs + r * 132 + c)       = make_float2(acc[mi][ni][0], acc[mi][ni][1]);
            *(float2*)(Cs + (r + 8) * 132 + c) = make_float2(acc[mi][ni][2], acc[mi][ni][3]);
        }
    __syncthreads();

    for (int idx = tid; idx < 128 * 32; idx += 512) {
        int row = idx >> 5, c = (idx & 31) * 4;
        if (c >= ncols) continue;
        float4 v = *(float4*)(Cs + row * 132 + c);
        float b = bias_s[row];
        v.x += b; v.y += b; v.z += b; v.w += b;
        if (!isRes) {
            __half2 h0 = __floats2half2_rn(v.x, v.y);
            __half2 h1 = __floats2half2_rn(v.z, v.w);
            uint2 pk; pk.x = *(unsigned*)&h0; pk.y = *(unsigned*)&h1;
            int cl = rem0 + c;
            int w = w0, t = cl;
            if (cl >= 300) { w = w0 + 1; t = cl - 300; }
            *(uint2*)(g_feat + ((size_t)(n * COUT + row) * 80 + rg * 25 + w) * FS + t) = pk;
        } else {
            *(float4*)(out + (size_t)(n * COUT + row) * VT + c0 + c) = v;
        }
    }
}

// ---------------------------------------------------------------------------
// kC_m: per (o, n): Out[25 x 300] = A[25 x 75] @ feat[75 x 300] (fp16 mma),
// then bn + residual + relu. Stagings = flat cp.async memcpys.
// ---------------------------------------------------------------------------
#define CSd 308
#define KCM_A   (80 * FS * 2)          // 49920
#define KCM_SMEM (KCM_A + 32 * 80 * 2) // 55040
__global__ void __launch_bounds__(256)
kC_m(const float* __restrict__ bn_g, const float* __restrict__ bn_b,
     const float* __restrict__ bn_m, const float* __restrict__ bn_v,
     float* __restrict__ out) {
    extern __shared__ char sm[];
    float* Cs = (float*)sm;

    int tid = threadIdx.x;
    int wid = tid >> 5, lane = tid & 31;
    int o = blockIdx.x, n = blockIdx.y;
    uint32_t sb = smem_u32(sm);

    // ---- stage feat + A: flat cp16 memcpys ----
    {
        const char* src = (const char*)(g_feat + (size_t)(n * COUT + o) * 80 * FS);
        for (int idx = tid; idx < 80 * FS * 2 / 16; idx += 256)
            cp16(sb + idx * 16, src + idx * 16);
        const char* srcA = (const char*)(g_Ah + (size_t)(n * COUT + o) * 32 * 80);
        for (int idx = tid; idx < 32 * 80 * 2 / 16; idx += 256)
            cp16(sb + KCM_A + idx * 16, srcA + idx * 16);
    }
    CP_COMMIT();
    CP_WAIT0();
    __syncthreads();

    int wn0 = wid * 40;

    float acc[2][5][4];
#pragma unroll
    for (int mi = 0; mi < 2; mi++)
#pragma unroll
        for (int ni = 0; ni < 5; ni++)
#pragma unroll
            for (int q = 0; q < 4; q++) acc[mi][ni][q] = 0.f;

#pragma unroll
    for (int k0 = 0; k0 < 80; k0 += 16) {
        uint32_t a[2][4];
#pragma unroll
        for (int mi = 0; mi < 2; mi++) {
            int row = mi * 16 + (lane & 15);
            int col = k0 + (lane >> 4) * 8;
            LDSM_X4(a[mi], sb + KCM_A + (uint32_t)(row * 80 + col) * 2);
        }
        uint32_t b[5][2];
#pragma unroll
        for (int ni = 0; ni < 5; ni++) {
            int krow = k0 + (lane & 15);
            LDSM_X2T(b[ni], sb + (uint32_t)(krow * FS + wn0 + ni * 8) * 2);
        }
#pragma unroll
        for (int mi = 0; mi < 2; mi++)
#pragma unroll
            for (int ni = 0; ni < 5; ni++)
                MMA_F16(acc[mi][ni], a[mi], b[ni]);
    }

    __syncthreads();

#pragma unroll
    for (int mi = 0; mi < 2; mi++)
#pragma unroll
        for (int ni = 0; ni < 5; ni++) {
            int c = wn0 + ni * 8 + (lane & 3) * 2;
            if (c < 304) {
                int r = mi * 16 + (lane >> 2);
                *(float2*)(Cs + r * CSd + c)       = make_float2(acc[mi][ni][0], acc[mi][ni][1]);
                *(float2*)(Cs + (r + 8) * CSd + c) = make_float2(acc[mi][ni][2], acc[mi][ni][3]);
            }
        }
    __syncthreads();

    float scale = bn_g[o] * rsqrtf(bn_v[o] + EPSf);
    float shift = bn_b[o] - bn_m[o] * scale;
    for (int idx = tid; idx < 25 * 75; idx += 256) {
        int v = idx / 75, t4 = (idx % 75) * 4;
        float4 g = *(float4*)(Cs + v * CSd + t4);
        float* op = out + ((size_t)n * COUT + o) * VT + v * 300 + t4;
        float4 r = *(float4*)op;
        r.x = fmaxf(fmaf(g.x, scale, shift) + r.x, 0.f);
        r.y = fmaxf(fmaf(g.y, scale, shift) + r.y, 0.f);
        r.z = fmaxf(fmaf(g.z, scale, shift) + r.z, 0.f);
        r.w = fmaxf(fmaf(g.w, scale, shift) + r.w, 0.f);
        *(float4*)op = r;
    }
}

// ---------------------------------------------------------------------------
extern "C" void kernel_launch(void* const* d_in, const int* in_sizes, int n_in,
                              void* d_out, int out_size) {
    const float* x       = (const float*)d_in[0];
    const float* ada_A   = (const float*)d_in[1];
    const float* PA      = (const float*)d_in[2];
    const float* conv3_w = (const float*)d_in[3];
    const float* conv3_b = (const float*)d_in[4];
    const float* ada_w   = (const float*)d_in[5];
    const float* ada_b   = (const float*)d_in[6];
    const float* bn_g    = (const float*)d_in[7];
    const float* bn_b    = (const float*)d_in[8];
    const float* bn_m    = (const float*)d_in[9];
    const float* bn_v    = (const float*)d_in[10];
    const float* down_w  = (const float*)d_in[11];
    const float* down_b  = (const float*)d_in[12];
    const float* dbn_g   = (const float*)d_in[13];
    const float* dbn_b   = (const float*)d_in[14];
    const float* dbn_m   = (const float*)d_in[15];
    const float* dbn_v   = (const float*)d_in[16];
    float* out = (float*)d_out;

    cudaFuncSetAttribute(kA,   cudaFuncAttributeMaxDynamicSharedMemorySize, KA_SMEM);
    cudaFuncSetAttribute(kB_m, cudaFuncAttributeMaxDynamicSharedMemorySize, KBM_SMEM);
    cudaFuncSetAttribute(kC_m, cudaFuncAttributeMaxDynamicSharedMemorySize, KCM_SMEM);

    kX<<<(Nn * CIN * VT / 4 + 255) / 256, 256>>>(x);
    kW<<<64, 512>>>(conv3_w, conv3_b, down_w, down_b, dbn_g, dbn_b, dbn_m, dbn_v);
    kA<<<dim3(20, Nn, Ss), 128, KA_SMEM>>>(ada_A, PA, ada_w, ada_b);
    kB_m<<<dim3(59, 4, Nn), 512, KBM_SMEM>>>(out);
    kC_m<<<dim3(COUT, Nn), 256, KCM_SMEM>>>(bn_g, bn_b, bn_m, bn_v, out);
}

// round 16
// speedup vs baseline: 1.4446x; 1.0559x over previous
#include <cuda_runtime.h>
#include <cuda_fp16.h>
#include <cuda_bf16.h>
#include <cstdint>

#define Nn   32
#define CIN  64
#define COUT 128
#define Vv   25
#define Tlen 300
#define Ss   3
#define VT   7500
#define VV   625
#define EPSf 1e-5f
#define FS   312   // padded feat row length (halves)

typedef unsigned long long u64;

// ---- device scratch (allocation-free) ----
__device__ __align__(16) __half g_feat[(size_t)Nn * COUT * 80 * FS];  // 204 MB
__device__ __align__(16) __half g_Ah[(size_t)Nn * COUT * 32 * 80];    // 21 MB
__device__ __align__(16) __half g_Xhi[Nn * CIN * VT];
__device__ __align__(16) __half g_Xlo[Nn * CIN * VT];
__device__ __align__(16) __half g_Whi[512 * 64];
__device__ __align__(16) __half g_Wlo[512 * 64];
__device__ __align__(16) float g_bias[512];

// ---- scalar/FMA2 helpers ----
__device__ __forceinline__ void fma2(u64& d, u64 a, u64 b) {
    asm("fma.rn.f32x2 %0, %1, %2, %0;" : "+l"(d) : "l"(a), "l"(b));
}
__device__ __forceinline__ u64 dup2(float v) {
    u64 r; asm("mov.b64 %0, {%1, %1};" : "=l"(r) : "f"(v)); return r;
}
__device__ __forceinline__ u64 pack2(float lo, float hi) {
    u64 r; asm("mov.b64 %0, {%1, %2};" : "=l"(r) : "f"(lo), "f"(hi)); return r;
}
__device__ __forceinline__ float lo32(u64 v) { return __uint_as_float((unsigned)v); }
__device__ __forceinline__ float hi32(u64 v) { return __uint_as_float((unsigned)(v >> 32)); }

__device__ __forceinline__ uint32_t smem_u32(const void* p) {
    uint32_t a;
    asm("{ .reg .u64 t; cvta.to.shared.u64 t, %1; cvt.u32.u64 %0, t; }" : "=r"(a) : "l"(p));
    return a;
}

// ---- cp.async (sm_80+) ----
__device__ __forceinline__ void cp16(uint32_t dst, const void* src) {
    asm volatile("cp.async.cg.shared.global [%0], [%1], 16;" :: "r"(dst), "l"(src));
}
__device__ __forceinline__ void cp8z(uint32_t dst, const void* src, bool pred) {
    int sz = pred ? 8 : 0;
    asm volatile("cp.async.ca.shared.global [%0], [%1], 8, %2;"
                 :: "r"(dst), "l"(src), "r"(sz));
}
__device__ __forceinline__ void cp4(uint32_t dst, const void* src) {
    asm volatile("cp.async.ca.shared.global [%0], [%1], 4;" :: "r"(dst), "l"(src));
}
#define CP_COMMIT() asm volatile("cp.async.commit_group;" ::: "memory")
#define CP_WAIT0()  asm volatile("cp.async.wait_group 0;" ::: "memory")

// ---- mma.sync / ldmatrix ----
#define LDSM_X4(r, addr) \
    asm volatile("ldmatrix.sync.aligned.m8n8.x4.shared.b16 {%0,%1,%2,%3}, [%4];" \
        : "=r"((r)[0]), "=r"((r)[1]), "=r"((r)[2]), "=r"((r)[3]) : "r"(addr))
#define LDSM_X2T(r, addr) \
    asm volatile("ldmatrix.sync.aligned.m8n8.x2.trans.shared.b16 {%0,%1}, [%2];" \
        : "=r"((r)[0]), "=r"((r)[1]) : "r"(addr))
#define MMA_F16(d, a, b) \
    asm volatile("mma.sync.aligned.m16n8k16.row.col.f32.f16.f16.f32 " \
        "{%0,%1,%2,%3}, {%4,%5,%6,%7}, {%8,%9}, {%0,%1,%2,%3};" \
        : "+f"((d)[0]), "+f"((d)[1]), "+f"((d)[2]), "+f"((d)[3]) \
        : "r"((a)[0]), "r"((a)[1]), "r"((a)[2]), "r"((a)[3]), "r"((b)[0]), "r"((b)[1]))

// ---------------------------------------------------------------------------
// kPrep: fused kX (split x into fp16 hi/lo) + kW (fold/split W + bias).
// blocks [0, XBLK): x split; blocks [XBLK, XBLK+128): W.
// ---------------------------------------------------------------------------
#define XBLK 15000
__global__ void kPrep(const float* __restrict__ x,
                      const float* __restrict__ conv3_w, const float* __restrict__ conv3_b,
                      const float* __restrict__ down_w,  const float* __restrict__ down_b,
                      const float* __restrict__ dg, const float* __restrict__ dbeta,
                      const float* __restrict__ dm, const float* __restrict__ dvar) {
    int bid = blockIdx.x;
    if (bid < XBLK) {
        size_t i4 = ((size_t)bid * blockDim.x + threadIdx.x) * 4;
        if (i4 >= (size_t)Nn * CIN * VT) return;
        float4 v = *(const float4*)(x + i4);
        __half h0 = __float2half_rn(v.x), h1 = __float2half_rn(v.y);
        __half h2 = __float2half_rn(v.z), h3 = __float2half_rn(v.w);
        __half2 p0(h0, h1), p1(h2, h3);
        uint2 ph; ph.x = *(unsigned*)&p0; ph.y = *(unsigned*)&p1;
        *(uint2*)(g_Xhi + i4) = ph;
        __half2 q0(__float2half_rn(v.x - __half2float(h0)), __float2half_rn(v.y - __half2float(h1)));
        __half2 q1(__float2half_rn(v.z - __half2float(h2)), __float2half_rn(v.w - __half2float(h3)));
        uint2 pl; pl.x = *(unsigned*)&q0; pl.y = *(unsigned*)&q1;
        *(uint2*)(g_Xlo + i4) = pl;
    } else {
        int idx = (bid - XBLK) * blockDim.x + threadIdx.x;
        if (idx >= 512 * 64) return;
        int r = idx >> 6, k = idx & 63;
        float w;
        if (r < Ss * COUT) {
            w = conv3_w[r * CIN + k];
        } else {
            int o = r - Ss * COUT;
            w = dg[o] * rsqrtf(dvar[o] + EPSf) * down_w[o * CIN + k];
        }
        __half hi = __float2half_rn(w);
        g_Whi[idx] = hi;
        g_Wlo[idx] = __float2half_rn(w - __half2float(hi));
        if (k == 0) {
            float b;
            if (r < Ss * COUT) b = conv3_b[r];
            else {
                int o = r - Ss * COUT;
                float sc = dg[o] * rsqrtf(dvar[o] + EPSf);
                b = sc * (down_b[o] - dm[o]) + dbeta[o];
            }
            g_bias[r] = b;
        }
    }
}

// ---------------------------------------------------------------------------
// kA: g_Ah[n][o][v][s*25+w] = fp16((ada_w . ada_A + ada_b) * PA).
// grid (20 = 5 vw-chunks x 4 o-groups, n, s), 128 threads, FMA2.
// Xa staged via cp.async (thread-per-column, 64 incremental cp4).
// ---------------------------------------------------------------------------
#define XA_OFF (64 * 16 * 8)                       // Wp 8192 bytes first
#define KA_SMEM (XA_OFF + 64 * 128 * 4 + 32 * 4)   // + Xa 32768 + bias 128
__global__ void __launch_bounds__(128)
kA(const float* __restrict__ adaA, const float* __restrict__ PA,
   const float* __restrict__ ada_w, const float* __restrict__ ada_b) {
    extern __shared__ char smA[];
    u64*   Wp  = (u64*)smA;
    float* Xa  = (float*)(smA + XA_OFF);            // [i*128 + j], 125 valid j
    float* bsm = (float*)(smA + XA_OFF + 64 * 128 * 4);

    int tid = threadIdx.x;
    int s = blockIdx.z, n = blockIdx.y;
    int g = blockIdx.x & 3;
    int vw0 = (blockIdx.x >> 2) * 125;
    uint32_t sbA = smem_u32(smA);

    // Xa via cp.async: thread tid handles column tid across all 64 i rows
    if (tid < 125) {
        const float* src = adaA + (size_t)(n * CIN) * VV + vw0 + tid;
        uint32_t dst = sbA + XA_OFF + tid * 4;
#pragma unroll 8
        for (int i = 0; i < 64; i++)
            cp4(dst + i * 128 * 4, src + (size_t)i * VV);
    }
    CP_COMMIT();

    const float* wsrc = ada_w + s * COUT * CIN + g * 32 * CIN;
    for (int idx = tid; idx < 64 * 16; idx += 128) {
        int i = idx >> 4, op = idx & 15;
        Wp[i * 16 + op] = pack2(wsrc[(2 * op) * CIN + i], wsrc[(2 * op + 1) * CIN + i]);
    }
    if (tid < 32) bsm[tid] = ada_b[s * COUT + g * 32 + tid];
    CP_WAIT0();
    __syncthreads();
    if (tid >= 125) return;

    int vw = vw0 + tid;
    int v = vw / 25, w = vw - v * 25;
    float pa = PA[s * VV + vw];

    u64 acc[16];
#pragma unroll
    for (int p = 0; p < 16; p++) acc[p] = 0ull;

#pragma unroll 8
    for (int i = 0; i < CIN; i++) {
        u64 f2 = dup2(Xa[i * 128 + tid]);
        const ulonglong2* wr = (const ulonglong2*)(Wp + i * 16);
#pragma unroll
        for (int p = 0; p < 8; p++) {
            ulonglong2 wv = wr[p];
            fma2(acc[2 * p],     wv.x, f2);
            fma2(acc[2 * p + 1], wv.y, f2);
        }
    }
    __half* outp = g_Ah + ((size_t)(n * COUT + g * 32) * 32 + v) * 80 + s * 25 + w;
#pragma unroll
    for (int p = 0; p < 16; p++) {
        outp[(size_t)(2 * p) * (32 * 80)]     = __float2half_rn((lo32(acc[p]) + bsm[2 * p])     * pa);
        outp[(size_t)(2 * p + 1) * (32 * 80)] = __float2half_rn((hi32(acc[p]) + bsm[2 * p + 1]) * pa);
    }
}

// ---------------------------------------------------------------------------
// kB_m: tensor GEMM C[128r x 128c] = W[128x64] @ X[64 x 128c].  (R15 verbatim)
// ---------------------------------------------------------------------------
#define PADK 72
#define PADC 136
#define WHI_OFF 0
#define WLO_OFF (128 * PADK * 2)
#define XHI_OFF (WLO_OFF + 128 * PADK * 2)
#define XLO_OFF (XHI_OFF + 64 * PADC * 2)
#define BIAS_OFF (XLO_OFF + 64 * PADC * 2)
#define KBM_SMEM (BIAS_OFF + 128 * 4)
__global__ void __launch_bounds__(512, 2)
kB_m(float* __restrict__ out) {
    extern __shared__ char sm[];
    float* bias_s = (float*)(sm + BIAS_OFF);
    float* Cs = (float*)sm;

    int tid = threadIdx.x;
    int wid = tid >> 5, lane = tid & 31;
    int n = blockIdx.z, rg = blockIdx.y;
    int c0 = blockIdx.x * 128;
    int r0 = rg * 128;
    int ncols = VT - c0; if (ncols > 128) ncols = 128;
    bool isRes = (rg == 3);
    int w0 = c0 / 300;
    int rem0 = c0 - w0 * 300;
    uint32_t sbase = smem_u32(sm);

    for (int idx = tid; idx < 1024; idx += 512) {
        int row = idx >> 3, kc = (idx & 7) * 8;
        cp16(sbase + WHI_OFF + (uint32_t)(row * PADK + kc) * 2,
             g_Whi + (size_t)(r0 + row) * 64 + kc);
    }
    if (isRes) {
        for (int idx = tid; idx < 1024; idx += 512) {
            int row = idx >> 3, kc = (idx & 7) * 8;
            cp16(sbase + WLO_OFF + (uint32_t)(row * PADK + kc) * 2,
                 g_Wlo + (size_t)(r0 + row) * 64 + kc);
        }
    }
    if (tid < 128) bias_s[tid] = g_bias[r0 + tid];

    for (int idx = tid; idx < 64 * 32; idx += 512) {
        int k = idx >> 5, c4 = (idx & 31) << 2;
        bool ok = (c4 < ncols);
        const __half* src = g_Xhi + (size_t)(n * CIN + k) * VT + c0 + (ok ? c4 : 0);
        cp8z(sbase + XHI_OFF + (uint32_t)(k * PADC + c4) * 2, src, ok);
        if (isRes) {
            const __half* srcl = g_Xlo + (size_t)(n * CIN + k) * VT + c0 + (ok ? c4 : 0);
            cp8z(sbase + XLO_OFF + (uint32_t)(k * PADC + c4) * 2, srcl, ok);
        }
    }
    CP_COMMIT();
    CP_WAIT0();
    __syncthreads();

    int wm0 = (wid & 3) * 32;
    int wn0 = (wid >> 2) * 32;

    float acc[2][4][4];
#pragma unroll
    for (int mi = 0; mi < 2; mi++)
#pragma unroll
        for (int ni = 0; ni < 4; ni++)
#pragma unroll
            for (int q = 0; q < 4; q++) acc[mi][ni][q] = 0.f;

#pragma unroll
    for (int k0 = 0; k0 < 64; k0 += 16) {
        uint32_t a_hi[2][4], b_hi[4][2];
#pragma unroll
        for (int mi = 0; mi < 2; mi++) {
            int row = wm0 + mi * 16 + (lane & 15);
            int col = k0 + (lane >> 4) * 8;
            LDSM_X4(a_hi[mi], sbase + WHI_OFF + (uint32_t)(row * PADK + col) * 2);
        }
#pragma unroll
        for (int ni = 0; ni < 4; ni++) {
            int krow = k0 + (lane & 15);
            LDSM_X2T(b_hi[ni], sbase + XHI_OFF + (uint32_t)(krow * PADC + wn0 + ni * 8) * 2);
        }
#pragma unroll
        for (int mi = 0; mi < 2; mi++)
#pragma unroll
            for (int ni = 0; ni < 4; ni++)
                MMA_F16(acc[mi][ni], a_hi[mi], b_hi[ni]);

        if (isRes) {
            uint32_t a_lo[2][4], b_lo[4][2];
#pragma unroll
            for (int mi = 0; mi < 2; mi++) {
                int row = wm0 + mi * 16 + (lane & 15);
                int col = k0 + (lane >> 4) * 8;
                LDSM_X4(a_lo[mi], sbase + WLO_OFF + (uint32_t)(row * PADK + col) * 2);
            }
#pragma unroll
            for (int ni = 0; ni < 4; ni++) {
                int krow = k0 + (lane & 15);
                LDSM_X2T(b_lo[ni], sbase + XLO_OFF + (uint32_t)(krow * PADC + wn0 + ni * 8) * 2);
            }
#pragma unroll
            for (int mi = 0; mi < 2; mi++)
#pragma unroll
                for (int ni = 0; ni < 4; ni++) {
                    MMA_F16(acc[mi][ni], a_hi[mi], b_lo[ni]);
                    MMA_F16(acc[mi][ni], a_lo[mi], b_hi[ni]);
                }
        }
    }

    __syncthreads();

#pragma unroll
    for (int mi = 0; mi < 2; mi++)
#pragma unroll
        for (int ni = 0; ni < 4; ni++) {
            int r = wm0 + mi * 16 + (lane >> 2);
            int c = wn0 + ni * 8 + (lane & 3) * 2;
            *(float2*)(Cs + r * 132 + c)       = make_float2(acc[mi][ni][0], acc[mi][ni][1]);
            *(float2*)(Cs + (r + 8) * 132 + c) = make_float2(acc[mi][ni][2], acc[mi][ni][3]);
        }
    __syncthreads();

    for (int idx = tid; idx < 128 * 32; idx += 512) {
        int row = idx >> 5, c = (idx & 31) * 4;
        if (c >= ncols) continue;
        float4 v = *(float4*)(Cs + row * 132 + c);
        float b = bias_s[row];
        v.x += b; v.y += b; v.z += b; v.w += b;
        if (!isRes) {
            __half2 h0 = __floats2half2_rn(v.x, v.y);
            __half2 h1 = __floats2half2_rn(v.z, v.w);
            uint2 pk; pk.x = *(unsigned*)&h0; pk.y = *(unsigned*)&h1;
            int cl = rem0 + c;
            int w = w0, t = cl;
            if (cl >= 300) { w = w0 + 1; t = cl - 300; }
            *(uint2*)(g_feat + ((size_t)(n * COUT + row) * 80 + rg * 25 + w) * FS + t) = pk;
        } else {
            *(float4*)(out + (size_t)(n * COUT + row) * VT + c0 + c) = v;
        }
    }
}

// ---------------------------------------------------------------------------
// kC_m: per (o, n): Out[25 x 300] = A[25 x 75] @ feat[75 x 300] (fp16 mma),
// then bn + residual + relu. Stagings = flat cp.async memcpys. (R15 verbatim)
// ---------------------------------------------------------------------------
#define CSd 308
#define KCM_A   (80 * FS * 2)          // 49920
#define KCM_SMEM (KCM_A + 32 * 80 * 2) // 55040
__global__ void __launch_bounds__(256)
kC_m(const float* __restrict__ bn_g, const float* __restrict__ bn_b,
     const float* __restrict__ bn_m, const float* __restrict__ bn_v,
     float* __restrict__ out) {
    extern __shared__ char sm[];
    float* Cs = (float*)sm;

    int tid = threadIdx.x;
    int wid = tid >> 5, lane = tid & 31;
    int o = blockIdx.x, n = blockIdx.y;
    uint32_t sb = smem_u32(sm);

    {
        const char* src = (const char*)(g_feat + (size_t)(n * COUT + o) * 80 * FS);
        for (int idx = tid; idx < 80 * FS * 2 / 16; idx += 256)
            cp16(sb + idx * 16, src + idx * 16);
        const char* srcA = (const char*)(g_Ah + (size_t)(n * COUT + o) * 32 * 80);
        for (int idx = tid; idx < 32 * 80 * 2 / 16; idx += 256)
            cp16(sb + KCM_A + idx * 16, srcA + idx * 16);
    }
    CP_COMMIT();
    CP_WAIT0();
    __syncthreads();

    int wn0 = wid * 40;

    float acc[2][5][4];
#pragma unroll
    for (int mi = 0; mi < 2; mi++)
#pragma unroll
        for (int ni = 0; ni < 5; ni++)
#pragma unroll
            for (int q = 0; q < 4; q++) acc[mi][ni][q] = 0.f;

#pragma unroll
    for (int k0 = 0; k0 < 80; k0 += 16) {
        uint32_t a[2][4];
#pragma unroll
        for (int mi = 0; mi < 2; mi++) {
            int row = mi * 16 + (lane & 15);
            int col = k0 + (lane >> 4) * 8;
            LDSM_X4(a[mi], sb + KCM_A + (uint32_t)(row * 80 + col) * 2);
        }
        uint32_t b[5][2];
#pragma unroll
        for (int ni = 0; ni < 5; ni++) {
            int krow = k0 + (lane & 15);
            LDSM_X2T(b[ni], sb + (uint32_t)(krow * FS + wn0 + ni * 8) * 2);
        }
#pragma unroll
        for (int mi = 0; mi < 2; mi++)
#pragma unroll
            for (int ni = 0; ni < 5; ni++)
                MMA_F16(acc[mi][ni], a[mi], b[ni]);
    }

    __syncthreads();

#pragma unroll
    for (int mi = 0; mi < 2; mi++)
#pragma unroll
        for (int ni = 0; ni < 5; ni++) {
            int c = wn0 + ni * 8 + (lane & 3) * 2;
            if (c < 304) {
                int r = mi * 16 + (lane >> 2);
                *(float2*)(Cs + r * CSd + c)       = make_float2(acc[mi][ni][0], acc[mi][ni][1]);
                *(float2*)(Cs + (r + 8) * CSd + c) = make_float2(acc[mi][ni][2], acc[mi][ni][3]);
            }
        }
    __syncthreads();

    float scale = bn_g[o] * rsqrtf(bn_v[o] + EPSf);
    float shift = bn_b[o] - bn_m[o] * scale;
    for (int idx = tid; idx < 25 * 75; idx += 256) {
        int v = idx / 75, t4 = (idx % 75) * 4;
        float4 g = *(float4*)(Cs + v * CSd + t4);
        float* op = out + ((size_t)n * COUT + o) * VT + v * 300 + t4;
        float4 r = *(float4*)op;
        r.x = fmaxf(fmaf(g.x, scale, shift) + r.x, 0.f);
        r.y = fmaxf(fmaf(g.y, scale, shift) + r.y, 0.f);
        r.z = fmaxf(fmaf(g.z, scale, shift) + r.z, 0.f);
        r.w = fmaxf(fmaf(g.w, scale, shift) + r.w, 0.f);
        *(float4*)op = r;
    }
}

// ---------------------------------------------------------------------------
extern "C" void kernel_launch(void* const* d_in, const int* in_sizes, int n_in,
                              void* d_out, int out_size) {
    const float* x       = (const float*)d_in[0];
    const float* ada_A   = (const float*)d_in[1];
    const float* PA      = (const float*)d_in[2];
    const float* conv3_w = (const float*)d_in[3];
    const float* conv3_b = (const float*)d_in[4];
    const float* ada_w   = (const float*)d_in[5];
    const float* ada_b   = (const float*)d_in[6];
    const float* bn_g    = (const float*)d_in[7];
    const float* bn_b    = (const float*)d_in[8];
    const float* bn_m    = (const float*)d_in[9];
    const float* bn_v    = (const float*)d_in[10];
    const float* down_w  = (const float*)d_in[11];
    const float* down_b  = (const float*)d_in[12];
    const float* dbn_g   = (const float*)d_in[13];
    const float* dbn_b   = (const float*)d_in[14];
    const float* dbn_m   = (const float*)d_in[15];
    const float* dbn_v   = (const float*)d_in[16];
    float* out = (float*)d_out;

    cudaFuncSetAttribute(kA,   cudaFuncAttributeMaxDynamicSharedMemorySize, KA_SMEM);
    cudaFuncSetAttribute(kB_m, cudaFuncAttributeMaxDynamicSharedMemorySize, KBM_SMEM);
    cudaFuncSetAttribute(kC_m, cudaFuncAttributeMaxDynamicSharedMemorySize, KCM_SMEM);

    kPrep<<<XBLK + 128, 256>>>(x, conv3_w, conv3_b, down_w, down_b,
                               dbn_g, dbn_b, dbn_m, dbn_v);
    kA<<<dim3(20, Nn, Ss), 128, KA_SMEM>>>(ada_A, PA, ada_w, ada_b);
    kB_m<<<dim3(59, 4, Nn), 512, KBM_SMEM>>>(out);
    kC_m<<<dim3(COUT, Nn), 256, KCM_SMEM>>>(bn_g, bn_b, bn_m, bn_v, out);
}

// round 17
// speedup vs baseline: 1.5321x; 1.0606x over previous
#include <cuda_runtime.h>
#include <cuda_fp16.h>
#include <cuda_bf16.h>
#include <cstdint>

#define Nn   32
#define CIN  64
#define COUT 128
#define Vv   25
#define Tlen 300
#define Ss   3
#define VT   7500
#define VV   625
#define EPSf 1e-5f
#define FS   312   // padded feat row length (halves)

typedef unsigned long long u64;

// ---- device scratch (allocation-free) ----
__device__ __align__(16) __half g_feat[(size_t)Nn * COUT * 80 * FS];  // 204 MB
__device__ __align__(16) __half g_Ah[(size_t)Nn * COUT * 32 * 80];    // 21 MB
__device__ __align__(16) __half g_Xhi[Nn * CIN * VT];
__device__ __align__(16) __half g_Xlo[Nn * CIN * VT];
__device__ __align__(16) __half g_Whi[512 * 64];
__device__ __align__(16) __half g_Wlo[512 * 64];
__device__ __align__(16) float g_bias[512];

// ---- scalar/FMA2 helpers ----
__device__ __forceinline__ void fma2(u64& d, u64 a, u64 b) {
    asm("fma.rn.f32x2 %0, %1, %2, %0;" : "+l"(d) : "l"(a), "l"(b));
}
__device__ __forceinline__ u64 dup2(float v) {
    u64 r; asm("mov.b64 %0, {%1, %1};" : "=l"(r) : "f"(v)); return r;
}
__device__ __forceinline__ u64 pack2(float lo, float hi) {
    u64 r; asm("mov.b64 %0, {%1, %2};" : "=l"(r) : "f"(lo), "f"(hi)); return r;
}
__device__ __forceinline__ float lo32(u64 v) { return __uint_as_float((unsigned)v); }
__device__ __forceinline__ float hi32(u64 v) { return __uint_as_float((unsigned)(v >> 32)); }

__device__ __forceinline__ uint32_t smem_u32(const void* p) {
    uint32_t a;
    asm("{ .reg .u64 t; cvta.to.shared.u64 t, %1; cvt.u32.u64 %0, t; }" : "=r"(a) : "l"(p));
    return a;
}

// ---- cp.async (sm_80+) ----
__device__ __forceinline__ void cp16(uint32_t dst, const void* src) {
    asm volatile("cp.async.cg.shared.global [%0], [%1], 16;" :: "r"(dst), "l"(src));
}
__device__ __forceinline__ void cp8z(uint32_t dst, const void* src, bool pred) {
    int sz = pred ? 8 : 0;
    asm volatile("cp.async.ca.shared.global [%0], [%1], 8, %2;"
                 :: "r"(dst), "l"(src), "r"(sz));
}
__device__ __forceinline__ void cp4(uint32_t dst, const void* src) {
    asm volatile("cp.async.ca.shared.global [%0], [%1], 4;" :: "r"(dst), "l"(src));
}
#define CP_COMMIT() asm volatile("cp.async.commit_group;" ::: "memory")
#define CP_WAIT0()  asm volatile("cp.async.wait_group 0;" ::: "memory")

// ---- mma.sync / ldmatrix ----
#define LDSM_X4(r, addr) \
    asm volatile("ldmatrix.sync.aligned.m8n8.x4.shared.b16 {%0,%1,%2,%3}, [%4];" \
        : "=r"((r)[0]), "=r"((r)[1]), "=r"((r)[2]), "=r"((r)[3]) : "r"(addr))
#define LDSM_X2T(r, addr) \
    asm volatile("ldmatrix.sync.aligned.m8n8.x2.trans.shared.b16 {%0,%1}, [%2];" \
        : "=r"((r)[0]), "=r"((r)[1]) : "r"(addr))
#define MMA_F16(d, a, b) \
    asm volatile("mma.sync.aligned.m16n8k16.row.col.f32.f16.f16.f32 " \
        "{%0,%1,%2,%3}, {%4,%5,%6,%7}, {%8,%9}, {%0,%1,%2,%3};" \
        : "+f"((d)[0]), "+f"((d)[1]), "+f"((d)[2]), "+f"((d)[3]) \
        : "r"((a)[0]), "r"((a)[1]), "r"((a)[2]), "r"((a)[3]), "r"((b)[0]), "r"((b)[1]))

// ---------------------------------------------------------------------------
// kPrep: fused x-split + W fold/split + bias.
// ---------------------------------------------------------------------------
#define XBLK 15000
__global__ void kPrep(const float* __restrict__ x,
                      const float* __restrict__ conv3_w, const float* __restrict__ conv3_b,
                      const float* __restrict__ down_w,  const float* __restrict__ down_b,
                      const float* __restrict__ dg, const float* __restrict__ dbeta,
                      const float* __restrict__ dm, const float* __restrict__ dvar) {
    int bid = blockIdx.x;
    if (bid < XBLK) {
        size_t i4 = ((size_t)bid * blockDim.x + threadIdx.x) * 4;
        if (i4 >= (size_t)Nn * CIN * VT) return;
        float4 v = *(const float4*)(x + i4);
        __half h0 = __float2half_rn(v.x), h1 = __float2half_rn(v.y);
        __half h2 = __float2half_rn(v.z), h3 = __float2half_rn(v.w);
        __half2 p0(h0, h1), p1(h2, h3);
        uint2 ph; ph.x = *(unsigned*)&p0; ph.y = *(unsigned*)&p1;
        *(uint2*)(g_Xhi + i4) = ph;
        __half2 q0(__float2half_rn(v.x - __half2float(h0)), __float2half_rn(v.y - __half2float(h1)));
        __half2 q1(__float2half_rn(v.z - __half2float(h2)), __float2half_rn(v.w - __half2float(h3)));
        uint2 pl; pl.x = *(unsigned*)&q0; pl.y = *(unsigned*)&q1;
        *(uint2*)(g_Xlo + i4) = pl;
    } else {
        int idx = (bid - XBLK) * blockDim.x + threadIdx.x;
        if (idx >= 512 * 64) return;
        int r = idx >> 6, k = idx & 63;
        float w;
        if (r < Ss * COUT) {
            w = conv3_w[r * CIN + k];
        } else {
            int o = r - Ss * COUT;
            w = dg[o] * rsqrtf(dvar[o] + EPSf) * down_w[o * CIN + k];
        }
        __half hi = __float2half_rn(w);
        g_Whi[idx] = hi;
        g_Wlo[idx] = __float2half_rn(w - __half2float(hi));
        if (k == 0) {
            float b;
            if (r < Ss * COUT) b = conv3_b[r];
            else {
                int o = r - Ss * COUT;
                float sc = dg[o] * rsqrtf(dvar[o] + EPSf);
                b = sc * (down_b[o] - dm[o]) + dbeta[o];
            }
            g_bias[r] = b;
        }
    }
}

// ---------------------------------------------------------------------------
// kA: g_Ah[n][o][v][s*25+w] = fp16((ada_w . ada_A + ada_b) * PA).
// ---------------------------------------------------------------------------
#define XA_OFF (64 * 16 * 8)
#define KA_SMEM (XA_OFF + 64 * 128 * 4 + 32 * 4)
__global__ void __launch_bounds__(128)
kA(const float* __restrict__ adaA, const float* __restrict__ PA,
   const float* __restrict__ ada_w, const float* __restrict__ ada_b) {
    extern __shared__ char smA[];
    u64*   Wp  = (u64*)smA;
    float* Xa  = (float*)(smA + XA_OFF);
    float* bsm = (float*)(smA + XA_OFF + 64 * 128 * 4);

    int tid = threadIdx.x;
    int s = blockIdx.z, n = blockIdx.y;
    int g = blockIdx.x & 3;
    int vw0 = (blockIdx.x >> 2) * 125;
    uint32_t sbA = smem_u32(smA);

    if (tid < 125) {
        const float* src = adaA + (size_t)(n * CIN) * VV + vw0 + tid;
        uint32_t dst = sbA + XA_OFF + tid * 4;
#pragma unroll 8
        for (int i = 0; i < 64; i++)
            cp4(dst + i * 128 * 4, src + (size_t)i * VV);
    }
    CP_COMMIT();

    const float* wsrc = ada_w + s * COUT * CIN + g * 32 * CIN;
    for (int idx = tid; idx < 64 * 16; idx += 128) {
        int i = idx >> 4, op = idx & 15;
        Wp[i * 16 + op] = pack2(wsrc[(2 * op) * CIN + i], wsrc[(2 * op + 1) * CIN + i]);
    }
    if (tid < 32) bsm[tid] = ada_b[s * COUT + g * 32 + tid];
    CP_WAIT0();
    __syncthreads();
    if (tid >= 125) return;

    int vw = vw0 + tid;
    int v = vw / 25, w = vw - v * 25;
    float pa = PA[s * VV + vw];

    u64 acc[16];
#pragma unroll
    for (int p = 0; p < 16; p++) acc[p] = 0ull;

#pragma unroll 8
    for (int i = 0; i < CIN; i++) {
        u64 f2 = dup2(Xa[i * 128 + tid]);
        const ulonglong2* wr = (const ulonglong2*)(Wp + i * 16);
#pragma unroll
        for (int p = 0; p < 8; p++) {
            ulonglong2 wv = wr[p];
            fma2(acc[2 * p],     wv.x, f2);
            fma2(acc[2 * p + 1], wv.y, f2);
        }
    }
    __half* outp = g_Ah + ((size_t)(n * COUT + g * 32) * 32 + v) * 80 + s * 25 + w;
#pragma unroll
    for (int p = 0; p < 16; p++) {
        outp[(size_t)(2 * p) * (32 * 80)]     = __float2half_rn((lo32(acc[p]) + bsm[2 * p])     * pa);
        outp[(size_t)(2 * p + 1) * (32 * 80)] = __float2half_rn((hi32(acc[p]) + bsm[2 * p + 1]) * pa);
    }
}

// ---------------------------------------------------------------------------
// kB_m: tensor GEMM C[128r x 128c] = W[128x64] @ X[64 x 128c].
// feat CTAs: bias+fp16 convert at fragment dump -> half Cs (half the smem
// epilogue traffic, zero-arithmetic relayout loop). res CTA: fp32 Cs path.
// ---------------------------------------------------------------------------
#define PADK 72
#define PADC 136
#define WHI_OFF 0
#define WLO_OFF (128 * PADK * 2)
#define XHI_OFF (WLO_OFF + 128 * PADK * 2)
#define XLO_OFF (XHI_OFF + 64 * PADC * 2)
#define BIAS_OFF (XLO_OFF + 64 * PADC * 2)
#define KBM_SMEM (BIAS_OFF + 128 * 4)
__global__ void __launch_bounds__(512, 2)
kB_m(float* __restrict__ out) {
    extern __shared__ char sm[];
    float* bias_s = (float*)(sm + BIAS_OFF);
    float*  Cs  = (float*)sm;      // res epilogue: [128][132] fp32
    __half* Csh = (__half*)sm;     // feat epilogue: [128][136] fp16

    int tid = threadIdx.x;
    int wid = tid >> 5, lane = tid & 31;
    int n = blockIdx.z, rg = blockIdx.y;
    int c0 = blockIdx.x * 128;
    int r0 = rg * 128;
    int ncols = VT - c0; if (ncols > 128) ncols = 128;
    bool isRes = (rg == 3);
    int w0 = c0 / 300;
    int rem0 = c0 - w0 * 300;
    uint32_t sbase = smem_u32(sm);

    for (int idx = tid; idx < 1024; idx += 512) {
        int row = idx >> 3, kc = (idx & 7) * 8;
        cp16(sbase + WHI_OFF + (uint32_t)(row * PADK + kc) * 2,
             g_Whi + (size_t)(r0 + row) * 64 + kc);
    }
    if (isRes) {
        for (int idx = tid; idx < 1024; idx += 512) {
            int row = idx >> 3, kc = (idx & 7) * 8;
            cp16(sbase + WLO_OFF + (uint32_t)(row * PADK + kc) * 2,
                 g_Wlo + (size_t)(r0 + row) * 64 + kc);
        }
    }
    if (tid < 128) bias_s[tid] = g_bias[r0 + tid];

    for (int idx = tid; idx < 64 * 32; idx += 512) {
        int k = idx >> 5, c4 = (idx & 31) << 2;
        bool ok = (c4 < ncols);
        const __half* src = g_Xhi + (size_t)(n * CIN + k) * VT + c0 + (ok ? c4 : 0);
        cp8z(sbase + XHI_OFF + (uint32_t)(k * PADC + c4) * 2, src, ok);
        if (isRes) {
            const __half* srcl = g_Xlo + (size_t)(n * CIN + k) * VT + c0 + (ok ? c4 : 0);
            cp8z(sbase + XLO_OFF + (uint32_t)(k * PADC + c4) * 2, srcl, ok);
        }
    }
    CP_COMMIT();
    CP_WAIT0();
    __syncthreads();

    int wm0 = (wid & 3) * 32;
    int wn0 = (wid >> 2) * 32;

    float acc[2][4][4];
#pragma unroll
    for (int mi = 0; mi < 2; mi++)
#pragma unroll
        for (int ni = 0; ni < 4; ni++)
#pragma unroll
            for (int q = 0; q < 4; q++) acc[mi][ni][q] = 0.f;

#pragma unroll
    for (int k0 = 0; k0 < 64; k0 += 16) {
        uint32_t a_hi[2][4], b_hi[4][2];
#pragma unroll
        for (int mi = 0; mi < 2; mi++) {
            int row = wm0 + mi * 16 + (lane & 15);
            int col = k0 + (lane >> 4) * 8;
            LDSM_X4(a_hi[mi], sbase + WHI_OFF + (uint32_t)(row * PADK + col) * 2);
        }
#pragma unroll
        for (int ni = 0; ni < 4; ni++) {
            int krow = k0 + (lane & 15);
            LDSM_X2T(b_hi[ni], sbase + XHI_OFF + (uint32_t)(krow * PADC + wn0 + ni * 8) * 2);
        }
#pragma unroll
        for (int mi = 0; mi < 2; mi++)
#pragma unroll
            for (int ni = 0; ni < 4; ni++)
                MMA_F16(acc[mi][ni], a_hi[mi], b_hi[ni]);

        if (isRes) {
            uint32_t a_lo[2][4], b_lo[4][2];
#pragma unroll
            for (int mi = 0; mi < 2; mi++) {
                int row = wm0 + mi * 16 + (lane & 15);
                int col = k0 + (lane >> 4) * 8;
                LDSM_X4(a_lo[mi], sbase + WLO_OFF + (uint32_t)(row * PADK + col) * 2);
            }
#pragma unroll
            for (int ni = 0; ni < 4; ni++) {
                int krow = k0 + (lane & 15);
                LDSM_X2T(b_lo[ni], sbase + XLO_OFF + (uint32_t)(krow * PADC + wn0 + ni * 8) * 2);
            }
#pragma unroll
            for (int mi = 0; mi < 2; mi++)
#pragma unroll
                for (int ni = 0; ni < 4; ni++) {
                    MMA_F16(acc[mi][ni], a_hi[mi], b_lo[ni]);
                    MMA_F16(acc[mi][ni], a_lo[mi], b_hi[ni]);
                }
        }
    }

    __syncthreads();

    if (!isRes) {
        // ---- fragment dump: bias + fp16 convert in registers -> half Cs ----
#pragma unroll
        for (int mi = 0; mi < 2; mi++) {
            int r = wm0 + mi * 16 + (lane >> 2);
            float b0 = bias_s[r], b1 = bias_s[r + 8];
            int c = wn0 + (lane & 3) * 2;
#pragma unroll
            for (int ni = 0; ni < 4; ni++) {
                __half2 h0 = __floats2half2_rn(acc[mi][ni][0] + b0, acc[mi][ni][1] + b0);
                __half2 h1 = __floats2half2_rn(acc[mi][ni][2] + b1, acc[mi][ni][3] + b1);
                *(__half2*)(Csh + r * 136 + c + ni * 8)       = h0;
                *(__half2*)(Csh + (r + 8) * 136 + c + ni * 8) = h1;
            }
        }
        __syncthreads();

        // ---- pure relayout: half Cs -> padded g_feat (uint2 = 4 halves) ----
        for (int idx = tid; idx < 128 * 32; idx += 512) {
            int row = idx >> 5, c = (idx & 31) * 4;
            if (c >= ncols) continue;
            uint2 pk = *(uint2*)(Csh + row * 136 + c);
            int cl = rem0 + c;
            int w = w0, t = cl;
            if (cl >= 300) { w = w0 + 1; t = cl - 300; }
            *(uint2*)(g_feat + ((size_t)(n * COUT + row) * 80 + rg * 25 + w) * FS + t) = pk;
        }
    } else {
#pragma unroll
        for (int mi = 0; mi < 2; mi++)
#pragma unroll
            for (int ni = 0; ni < 4; ni++) {
                int r = wm0 + mi * 16 + (lane >> 2);
                int c = wn0 + ni * 8 + (lane & 3) * 2;
                *(float2*)(Cs + r * 132 + c)       = make_float2(acc[mi][ni][0], acc[mi][ni][1]);
                *(float2*)(Cs + (r + 8) * 132 + c) = make_float2(acc[mi][ni][2], acc[mi][ni][3]);
            }
        __syncthreads();

        for (int idx = tid; idx < 128 * 32; idx += 512) {
            int row = idx >> 5, c = (idx & 31) * 4;
            if (c >= ncols) continue;
            float4 v = *(float4*)(Cs + row * 132 + c);
            float b = bias_s[row];
            v.x += b; v.y += b; v.z += b; v.w += b;
            *(float4*)(out + (size_t)(n * COUT + row) * VT + c0 + c) = v;
        }
    }
}

// ---------------------------------------------------------------------------
// kC_m: per (o, n): Out[25 x 300] = A[25 x 75] @ feat[75 x 300] (fp16 mma),
// then bn + residual + relu. (R16 verbatim)
// ---------------------------------------------------------------------------
#define CSd 308
#define KCM_A   (80 * FS * 2)
#define KCM_SMEM (KCM_A + 32 * 80 * 2)
__global__ void __launch_bounds__(256)
kC_m(const float* __restrict__ bn_g, const float* __restrict__ bn_b,
     const float* __restrict__ bn_m, const float* __restrict__ bn_v,
     float* __restrict__ out) {
    extern __shared__ char sm[];
    float* Cs = (float*)sm;

    int tid = threadIdx.x;
    int wid = tid >> 5, lane = tid & 31;
    int o = blockIdx.x, n = blockIdx.y;
    uint32_t sb = smem_u32(sm);

    {
        const char* src = (const char*)(g_feat + (size_t)(n * COUT + o) * 80 * FS);
        for (int idx = tid; idx < 80 * FS * 2 / 16; idx += 256)
            cp16(sb + idx * 16, src + idx * 16);
        const char* srcA = (const char*)(g_Ah + (size_t)(n * COUT + o) * 32 * 80);
        for (int idx = tid; idx < 32 * 80 * 2 / 16; idx += 256)
            cp16(sb + KCM_A + idx * 16, srcA + idx * 16);
    }
    CP_COMMIT();
    CP_WAIT0();
    __syncthreads();

    int wn0 = wid * 40;

    float acc[2][5][4];
#pragma unroll
    for (int mi = 0; mi < 2; mi++)
#pragma unroll
        for (int ni = 0; ni < 5; ni++)
#pragma unroll
            for (int q = 0; q < 4; q++) acc[mi][ni][q] = 0.f;

#pragma unroll
    for (int k0 = 0; k0 < 80; k0 += 16) {
        uint32_t a[2][4];
#pragma unroll
        for (int mi = 0; mi < 2; mi++) {
            int row = mi * 16 + (lane & 15);
            int col = k0 + (lane >> 4) * 8;
            LDSM_X4(a[mi], sb + KCM_A + (uint32_t)(row * 80 + col) * 2);
        }
        uint32_t b[5][2];
#pragma unroll
        for (int ni = 0; ni < 5; ni++) {
            int krow = k0 + (lane & 15);
            LDSM_X2T(b[ni], sb + (uint32_t)(krow * FS + wn0 + ni * 8) * 2);
        }
#pragma unroll
        for (int mi = 0; mi < 2; mi++)
#pragma unroll
            for (int ni = 0; ni < 5; ni++)
                MMA_F16(acc[mi][ni], a[mi], b[ni]);
    }

    __syncthreads();

#pragma unroll
    for (int mi = 0; mi < 2; mi++)
#pragma unroll
        for (int ni = 0; ni < 5; ni++) {
            int c = wn0 + ni * 8 + (lane & 3) * 2;
            if (c < 304) {
                int r = mi * 16 + (lane >> 2);
                *(float2*)(Cs + r * CSd + c)       = make_float2(acc[mi][ni][0], acc[mi][ni][1]);
                *(float2*)(Cs + (r + 8) * CSd + c) = make_float2(acc[mi][ni][2], acc[mi][ni][3]);
            }
        }
    __syncthreads();

    float scale = bn_g[o] * rsqrtf(bn_v[o] + EPSf);
    float shift = bn_b[o] - bn_m[o] * scale;
    for (int idx = tid; idx < 25 * 75; idx += 256) {
        int v = idx / 75, t4 = (idx % 75) * 4;
        float4 g = *(float4*)(Cs + v * CSd + t4);
        float* op = out + ((size_t)n * COUT + o) * VT + v * 300 + t4;
        float4 r = *(float4*)op;
        r.x = fmaxf(fmaf(g.x, scale, shift) + r.x, 0.f);
        r.y = fmaxf(fmaf(g.y, scale, shift) + r.y, 0.f);
        r.z = fmaxf(fmaf(g.z, scale, shift) + r.z, 0.f);
        r.w = fmaxf(fmaf(g.w, scale, shift) + r.w, 0.f);
        *(float4*)op = r;
    }
}

// ---------------------------------------------------------------------------
extern "C" void kernel_launch(void* const* d_in, const int* in_sizes, int n_in,
                              void* d_out, int out_size) {
    const float* x       = (const float*)d_in[0];
    const float* ada_A   = (const float*)d_in[1];
    const float* PA      = (const float*)d_in[2];
    const float* conv3_w = (const float*)d_in[3];
    const float* conv3_b = (const float*)d_in[4];
    const float* ada_w   = (const float*)d_in[5];
    const float* ada_b   = (const float*)d_in[6];
    const float* bn_g    = (const float*)d_in[7];
    const float* bn_b    = (const float*)d_in[8];
    const float* bn_m    = (const float*)d_in[9];
    const float* bn_v    = (const float*)d_in[10];
    const float* down_w  = (const float*)d_in[11];
    const float* down_b  = (const float*)d_in[12];
    const float* dbn_g   = (const float*)d_in[13];
    const float* dbn_b   = (const float*)d_in[14];
    const float* dbn_m   = (const float*)d_in[15];
    const float* dbn_v   = (const float*)d_in[16];
    float* out = (float*)d_out;

    cudaFuncSetAttribute(kA,   cudaFuncAttributeMaxDynamicSharedMemorySize, KA_SMEM);
    cudaFuncSetAttribute(kB_m, cudaFuncAttributeMaxDynamicSharedMemorySize, KBM_SMEM);
    cudaFuncSetAttribute(kC_m, cudaFuncAttributeMaxDynamicSharedMemorySize, KCM_SMEM);

    kPrep<<<XBLK + 128, 256>>>(x, conv3_w, conv3_b, down_w, down_b,
                               dbn_g, dbn_b, dbn_m, dbn_v);
    kA<<<dim3(20, Nn, Ss), 128, KA_SMEM>>>(ada_A, PA, ada_w, ada_b);
    kB_m<<<dim3(59, 4, Nn), 512, KBM_SMEM>>>(out);
    kC_m<<<dim3(COUT, Nn), 256, KCM_SMEM>>>(bn_g, bn_b, bn_m, bn_v, out);
}